// round 7
// baseline (speedup 1.0000x reference)
#include <cuda_runtime.h>
#include <cuda_bf16.h>
#include <math.h>

#define N_NODES 100000
#define E_EDGES 1600000
#define FDIM    128
#define GGRAPHS 64
#define COUT    10
#define SROW    24          // smem row stride in bf16 (16 data + 8 pad)

// -------------------- scratch (static device globals) -----------------------
__device__ int   g_deg[N_NODES];
__device__ int   g_rowptr[N_NODES + 1];
__device__ int   g_cursor[N_NODES];
__device__ int   g_csr[E_EDGES];
__device__ __align__(16) __nv_bfloat16 g_ahi[(size_t)N_NODES * FDIM];
__device__ __align__(16) __nv_bfloat16 g_alo[(size_t)N_NODES * FDIM];
__device__ __align__(16) __nv_bfloat16 g_whi[3 * 256 * FDIM];
__device__ __align__(16) __nv_bfloat16 g_wlo[3 * 256 * FDIM];
__device__ float g_xr[(size_t)N_NODES * FDIM];
__device__ float g_xo[(size_t)N_NODES * FDIM];
__device__ float g_hA[(size_t)N_NODES * FDIM];
__device__ float g_pooled[GGRAPHS * FDIM];

// permuted position of k within a 16-wide tile group:
// groups g hold k = {2g, 2g+1, 2g+8, 2g+9} at positions 4g..4g+3
__device__ __forceinline__ int gpos(int k) {
    int t = k >> 4, kk = k & 15;
    return t * 16 + 4 * ((kk & 7) >> 1) + 2 * ((kk >> 3) & 1) + (kk & 1);
}

// -------------------- CSR build ---------------------------------------------
__global__ void k_zero_deg() {
    int i = blockIdx.x * blockDim.x + threadIdx.x;
    if (i < N_NODES) g_deg[i] = 0;
}

__global__ void k_hist(const int* __restrict__ ei) {
    int e = blockIdx.x * blockDim.x + threadIdx.x;
    if (e < E_EDGES) atomicAdd(&g_deg[ei[E_EDGES + e]], 1);
}

__global__ void k_scan() {
    __shared__ int tsum[1024];
    const int T = 1024;
    int tid = threadIdx.x;
    int per = (N_NODES + T - 1) / T;
    int b = tid * per;
    int e = min(b + per, N_NODES);
    int s = 0;
    for (int i = b; i < e; i++) s += g_deg[i];
    tsum[tid] = s;
    __syncthreads();
    for (int d = 1; d < T; d <<= 1) {
        int v = (tid >= d) ? tsum[tid - d] : 0;
        __syncthreads();
        tsum[tid] += v;
        __syncthreads();
    }
    int off = (tid == 0) ? 0 : tsum[tid - 1];
    for (int i = b; i < e; i++) {
        g_rowptr[i] = off;
        g_cursor[i] = off;
        off += g_deg[i];
    }
    if (tid == T - 1) g_rowptr[N_NODES] = off;
}

__global__ void k_fill(const int* __restrict__ ei) {
    int e = blockIdx.x * blockDim.x + threadIdx.x;
    if (e < E_EDGES) {
        int d = ei[E_EDGES + e];
        int p = atomicAdd(&g_cursor[d], 1);
        g_csr[p] = ei[e];
    }
}

// -------------------- precompute split planes -------------------------------
__global__ void k_split_w(const float* __restrict__ Wr,
                          const float* __restrict__ Wo, int layer) {
    int row = blockIdx.x;           // 0..255 (0-127 Wr, 128-255 Wo)
    int k = threadIdx.x;            // 0..127
    const float* src = (row < 128) ? (Wr + (size_t)row * FDIM)
                                   : (Wo + (size_t)(row - 128) * FDIM);
    float v = src[k];
    __nv_bfloat16 h = __float2bfloat16(v);
    __nv_bfloat16 l = __float2bfloat16(v - __bfloat162float(h));
    int idx = layer * 256 * FDIM + row * FDIM + gpos(k);
    g_whi[idx] = h;
    g_wlo[idx] = l;
}

__global__ void k_split_x(const float* __restrict__ x) {
    int node = blockIdx.x * 2 + (threadIdx.x >> 7);
    int k = threadIdx.x & 127;
    float v = x[(size_t)node * FDIM + k];
    __nv_bfloat16 h = __float2bfloat16(v);
    __nv_bfloat16 l = __float2bfloat16(v - __bfloat162float(h));
    size_t idx = (size_t)node * FDIM + gpos(k);
    g_ahi[idx] = h;
    g_alo[idx] = l;
}

// ===================== dual bf16-split GEMM =================================
// xr = A @ Wr^T, xo = A @ Wo^T. A split planes in g_ahi/g_alo (k-permuted);
// W split planes in g_whi/g_wlo. 3 products hh+hl+lh, fp32 accumulate.
__device__ __forceinline__ void mma16(float* c, const unsigned* a,
                                      unsigned b0, unsigned b1) {
    asm volatile(
        "mma.sync.aligned.m16n8k16.row.col.f32.bf16.bf16.f32 "
        "{%0,%1,%2,%3},{%4,%5,%6,%7},{%8,%9},{%0,%1,%2,%3};"
        : "+f"(c[0]), "+f"(c[1]), "+f"(c[2]), "+f"(c[3])
        : "r"(a[0]), "r"(a[1]), "r"(a[2]), "r"(a[3]), "r"(b0), "r"(b1));
}

__global__ __launch_bounds__(256) void k_gemm_dual(int layer, int M)
{
    __shared__ __align__(16) __nv_bfloat16 sAh[128 * SROW];
    __shared__ __align__(16) __nv_bfloat16 sAl[128 * SROW];
    __shared__ __align__(16) __nv_bfloat16 sBh[256 * SROW];
    __shared__ __align__(16) __nv_bfloat16 sBl[256 * SROW];

    int tid = threadIdx.x;
    int m0 = blockIdx.x * 128;
    int warp = tid >> 5, lane = tid & 31;
    int wm = warp >> 1, wn = warp & 1;
    int gq = lane >> 2, t4 = lane & 3;

    const __nv_bfloat16* Whi = g_whi + layer * 256 * FDIM;
    const __nv_bfloat16* Wlo = g_wlo + layer * 256 * FDIM;

    // staging mapping: A: 1 chunk per plane per thread; B: 2 chunks per plane
    int ar = tid >> 1, ac = tid & 1;       // row 0..127, 16B-chunk 0..1
    bool aok = (m0 + ar) < M;
    size_t abase = (size_t)(m0 + ar) * FDIM + ac * 8;
    int n0 = tid >> 1;                     // W row 0..127 (Wr)
    int n1 = 128 + n0;                     // W row 128..255 (Wo)
    size_t b0base = (size_t)n0 * FDIM + ac * 8;
    size_t b1base = (size_t)n1 * FDIM + ac * 8;

    uint4 stA0, stA1, stB0, stB1, stB2, stB3;
    const uint4 z4 = make_uint4(0, 0, 0, 0);

#define LOADI(i) do {                                                       \
        stA0 = aok ? *(const uint4*)(g_ahi + abase + (i) * 16) : z4;        \
        stA1 = aok ? *(const uint4*)(g_alo + abase + (i) * 16) : z4;        \
        stB0 = *(const uint4*)(Whi + b0base + (i) * 16);                    \
        stB1 = *(const uint4*)(Whi + b1base + (i) * 16);                    \
        stB2 = *(const uint4*)(Wlo + b0base + (i) * 16);                    \
        stB3 = *(const uint4*)(Wlo + b1base + (i) * 16);                    \
    } while (0)

    float accR[2][8][4], accO[2][8][4];
#pragma unroll
    for (int i = 0; i < 2; i++)
#pragma unroll
        for (int j = 0; j < 8; j++)
#pragma unroll
            for (int q = 0; q < 4; q++) { accR[i][j][q] = 0.f; accO[i][j][q] = 0.f; }

    LOADI(0);
#pragma unroll
    for (int it = 0; it < 8; it++) {
        __syncthreads();
        *(uint4*)(sAh + ar * SROW + ac * 8) = stA0;
        *(uint4*)(sAl + ar * SROW + ac * 8) = stA1;
        *(uint4*)(sBh + n0 * SROW + ac * 8) = stB0;
        *(uint4*)(sBh + n1 * SROW + ac * 8) = stB1;
        *(uint4*)(sBl + n0 * SROW + ac * 8) = stB2;
        *(uint4*)(sBl + n1 * SROW + ac * 8) = stB3;
        __syncthreads();
        if (it < 7) LOADI(it + 1);

        // A fragments: one LDS.64 per (row, plane)
        unsigned ah[2][4], al[2][4];
#pragma unroll
        for (int mt = 0; mt < 2; mt++) {
            int r = wm * 32 + mt * 16 + gq;
            uint2 v0 = *(const uint2*)(sAh + r * SROW + 4 * t4);
            uint2 v1 = *(const uint2*)(sAh + (r + 8) * SROW + 4 * t4);
            ah[mt][0] = v0.x; ah[mt][1] = v1.x; ah[mt][2] = v0.y; ah[mt][3] = v1.y;
            uint2 w0 = *(const uint2*)(sAl + r * SROW + 4 * t4);
            uint2 w1 = *(const uint2*)(sAl + (r + 8) * SROW + 4 * t4);
            al[mt][0] = w0.x; al[mt][1] = w1.x; al[mt][2] = w0.y; al[mt][3] = w1.y;
        }
#pragma unroll
        for (int nt = 0; nt < 8; nt++) {
            int nR = wn * 64 + nt * 8 + gq;
            uint2 bh = *(const uint2*)(sBh + nR * SROW + 4 * t4);
            uint2 bl = *(const uint2*)(sBl + nR * SROW + 4 * t4);
            uint2 ch = *(const uint2*)(sBh + (nR + 128) * SROW + 4 * t4);
            uint2 cl = *(const uint2*)(sBl + (nR + 128) * SROW + 4 * t4);
#pragma unroll
            for (int mt = 0; mt < 2; mt++) {
                mma16(accR[mt][nt], al[mt], bh.x, bh.y);
                mma16(accR[mt][nt], ah[mt], bl.x, bl.y);
                mma16(accR[mt][nt], ah[mt], bh.x, bh.y);
                mma16(accO[mt][nt], al[mt], ch.x, ch.y);
                mma16(accO[mt][nt], ah[mt], cl.x, cl.y);
                mma16(accO[mt][nt], ah[mt], ch.x, ch.y);
            }
        }
    }
#undef LOADI

#pragma unroll
    for (int mt = 0; mt < 2; mt++) {
#pragma unroll
        for (int nt = 0; nt < 8; nt++) {
            int r0 = m0 + wm * 32 + mt * 16 + gq;
            int cc = wn * 64 + nt * 8 + t4 * 2;
            if (r0 < M) {
                float2 o;
                o.x = accR[mt][nt][0]; o.y = accR[mt][nt][1];
                *(float2*)(g_xr + (size_t)r0 * FDIM + cc) = o;
                o.x = accO[mt][nt][0]; o.y = accO[mt][nt][1];
                *(float2*)(g_xo + (size_t)r0 * FDIM + cc) = o;
            }
            if (r0 + 8 < M) {
                float2 o;
                o.x = accR[mt][nt][2]; o.y = accR[mt][nt][3];
                *(float2*)(g_xr + (size_t)(r0 + 8) * FDIM + cc) = o;
                o.x = accO[mt][nt][2]; o.y = accO[mt][nt][3];
                *(float2*)(g_xo + (size_t)(r0 + 8) * FDIM + cc) = o;
            }
        }
    }
}

// ----- fused: h_i = relu( sum_{j->i} xr[j] + xo[i] + bias ) -----------------
// mode 0: write split bf16 planes (g_ahi/g_alo, k-permuted) for next GEMM
// mode 1: write fp32 to outF (last layer, consumed by pool)
__global__ void k_agg(const float* __restrict__ xr,
                      const float* __restrict__ xo,
                      const float* __restrict__ bias,
                      float* __restrict__ outF, int mode)
{
    int node = (blockIdx.x * blockDim.x + threadIdx.x) >> 5;
    if (node >= N_NODES) return;
    int lane = threadIdx.x & 31;
    int beg = g_rowptr[node];
    int end = g_rowptr[node + 1];
    float4 a0 = make_float4(0.f, 0.f, 0.f, 0.f);
    float4 a1 = make_float4(0.f, 0.f, 0.f, 0.f);
    int e = beg;
    for (; e + 4 <= end; e += 4) {
        int s0 = g_csr[e], s1 = g_csr[e + 1], s2 = g_csr[e + 2], s3 = g_csr[e + 3];
        float4 v0 = __ldg((const float4*)(xr + (size_t)s0 * FDIM) + lane);
        float4 v1 = __ldg((const float4*)(xr + (size_t)s1 * FDIM) + lane);
        float4 v2 = __ldg((const float4*)(xr + (size_t)s2 * FDIM) + lane);
        float4 v3 = __ldg((const float4*)(xr + (size_t)s3 * FDIM) + lane);
        a0.x += v0.x + v1.x; a0.y += v0.y + v1.y;
        a0.z += v0.z + v1.z; a0.w += v0.w + v1.w;
        a1.x += v2.x + v3.x; a1.y += v2.y + v3.y;
        a1.z += v2.z + v3.z; a1.w += v2.w + v3.w;
    }
    for (; e < end; e++) {
        int s0 = g_csr[e];
        float4 v0 = __ldg((const float4*)(xr + (size_t)s0 * FDIM) + lane);
        a0.x += v0.x; a0.y += v0.y; a0.z += v0.z; a0.w += v0.w;
    }
    float4 o = __ldg((const float4*)(xo + (size_t)node * FDIM) + lane);
    float4 b = __ldg((const float4*)bias + lane);
    float4 r;
    r.x = fmaxf(a0.x + a1.x + o.x + b.x, 0.f);
    r.y = fmaxf(a0.y + a1.y + o.y + b.y, 0.f);
    r.z = fmaxf(a0.z + a1.z + o.z + b.z, 0.f);
    r.w = fmaxf(a0.w + a1.w + o.w + b.w, 0.f);

    if (mode == 0) {
        // split + permuted store: k0 = lane*4; pairs at pos1 and pos1+4
        int k0 = lane * 4;
        int tile = k0 >> 4, kk = k0 & 15;
        int pos1 = tile * 16 + 4 * ((kk & 7) >> 1) + 2 * ((kk >> 3) & 1);
        size_t base = (size_t)node * FDIM;
        __nv_bfloat162 h1 = __floats2bfloat162_rn(r.x, r.y);
        __nv_bfloat162 h2 = __floats2bfloat162_rn(r.z, r.w);
        float e1x = r.x - __bfloat162float(__low2bfloat16(h1));
        float e1y = r.y - __bfloat162float(__high2bfloat16(h1));
        float e2x = r.z - __bfloat162float(__low2bfloat16(h2));
        float e2y = r.w - __bfloat162float(__high2bfloat16(h2));
        __nv_bfloat162 l1 = __floats2bfloat162_rn(e1x, e1y);
        __nv_bfloat162 l2 = __floats2bfloat162_rn(e2x, e2y);
        *(unsigned*)(g_ahi + base + pos1)     = *(unsigned*)&h1;
        *(unsigned*)(g_ahi + base + pos1 + 4) = *(unsigned*)&h2;
        *(unsigned*)(g_alo + base + pos1)     = *(unsigned*)&l1;
        *(unsigned*)(g_alo + base + pos1 + 4) = *(unsigned*)&l2;
    } else {
        ((float4*)(outF + (size_t)node * FDIM))[lane] = r;
    }
}

// -------------------- mean pool (sorted batch ids, 4 row-stripes) -----------
__global__ void k_pool(const float* __restrict__ h, const int* __restrict__ batch) {
    int g = blockIdx.x;
    int t = threadIdx.x;                 // 0..511
    int col = t & 127, stripe = t >> 7;
    int lo, hi;
    {
        int key = g;
        int a = 0, b = N_NODES;
        while (a < b) { int m = (a + b) >> 1; if (batch[m] < key) a = m + 1; else b = m; }
        lo = a;
        key = g + 1; a = lo; b = N_NODES;
        while (a < b) { int m = (a + b) >> 1; if (batch[m] < key) a = m + 1; else b = m; }
        hi = a;
    }
    float s = 0.f;
    for (int n = lo + stripe; n < hi; n += 4) s += h[(size_t)n * FDIM + col];
    __shared__ float red[4][FDIM];
    red[stripe][col] = s;
    __syncthreads();
    if (stripe == 0) {
        float tot = red[0][col] + red[1][col] + red[2][col] + red[3][col];
        float c = (float)max(hi - lo, 1);
        g_pooled[g * FDIM + col] = tot / c;
    }
}

// -------------------- MLP head + log_softmax --------------------------------
__global__ void k_mlp(const float* __restrict__ Wl1, const float* __restrict__ bl1,
                      const float* __restrict__ Wl2, const float* __restrict__ bl2,
                      float* __restrict__ out)
{
    int g = blockIdx.x;
    int t = threadIdx.x;
    __shared__ float p[FDIM];
    __shared__ float h1[64];
    __shared__ float lg[COUT];
    p[t]      = g_pooled[g * FDIM + t];
    p[t + 64] = g_pooled[g * FDIM + 64 + t];
    __syncthreads();
    float s = bl1[t];
#pragma unroll 8
    for (int k = 0; k < FDIM; k++) s += p[k] * Wl1[t * FDIM + k];
    h1[t] = fmaxf(s, 0.f);
    __syncthreads();
    if (t < COUT) {
        float s2 = bl2[t];
#pragma unroll 8
        for (int k = 0; k < 64; k++) s2 += h1[k] * Wl2[t * 64 + k];
        lg[t] = s2;
    }
    __syncthreads();
    if (t == 0) {
        float mx = -INFINITY;
        for (int c = 0; c < COUT; c++) mx = fmaxf(mx, lg[c]);
        float se = 0.f;
        for (int c = 0; c < COUT; c++) se += expf(lg[c] - mx);
        float lse = logf(se) + mx;
        for (int c = 0; c < COUT; c++) out[g * COUT + c] = lg[c] - lse;
    }
}

// -------------------- launch ------------------------------------------------
extern "C" void kernel_launch(void* const* d_in, const int* in_sizes, int n_in,
                              void* d_out, int out_size)
{
    const float* x     = (const float*)d_in[0];
    const int*   ei    = (const int*)d_in[1];
    const int*   batch = (const int*)d_in[2];
    int wb = 3;
    if (n_in > 3 && in_sizes[3] <= 4) wb = 4;
    const float* W1r = (const float*)d_in[wb + 0];
    const float* b1  = (const float*)d_in[wb + 1];
    const float* W1o = (const float*)d_in[wb + 2];
    const float* W2r = (const float*)d_in[wb + 3];
    const float* b2  = (const float*)d_in[wb + 4];
    const float* W2o = (const float*)d_in[wb + 5];
    const float* W3r = (const float*)d_in[wb + 6];
    const float* b3  = (const float*)d_in[wb + 7];
    const float* W3o = (const float*)d_in[wb + 8];
    const float* Wl1 = (const float*)d_in[wb + 9];
    const float* bl1 = (const float*)d_in[wb + 10];
    const float* Wl2 = (const float*)d_in[wb + 11];
    const float* bl2 = (const float*)d_in[wb + 12];
    float* out = (float*)d_out;

    float *xr, *xo, *hA;
    cudaGetSymbolAddress((void**)&xr, g_xr);
    cudaGetSymbolAddress((void**)&xo, g_xo);
    cudaGetSymbolAddress((void**)&hA, g_hA);

    // prep: weight + input split planes
    k_split_w<<<256, 128>>>(W1r, W1o, 0);
    k_split_w<<<256, 128>>>(W2r, W2o, 1);
    k_split_w<<<256, 128>>>(W3r, W3o, 2);
    k_split_x<<<N_NODES / 2, 256>>>(x);

    // CSR build (once, reused by all 3 layers)
    k_zero_deg<<<(N_NODES + 255) / 256, 256>>>();
    k_hist<<<(E_EDGES + 255) / 256, 256>>>(ei);
    k_scan<<<1, 1024>>>();
    k_fill<<<(E_EDGES + 255) / 256, 256>>>(ei);

    int gemmBlocks = (N_NODES + 127) / 128;
    int aggBlocks  = (N_NODES * 32 + 255) / 256;

    // layer 1
    k_gemm_dual<<<gemmBlocks, 256>>>(0, N_NODES);
    k_agg<<<aggBlocks, 256>>>(xr, xo, b1, nullptr, 0);
    // layer 2
    k_gemm_dual<<<gemmBlocks, 256>>>(1, N_NODES);
    k_agg<<<aggBlocks, 256>>>(xr, xo, b2, nullptr, 0);
    // layer 3
    k_gemm_dual<<<gemmBlocks, 256>>>(2, N_NODES);
    k_agg<<<aggBlocks, 256>>>(xr, xo, b3, hA, 1);

    // pool + head
    k_pool<<<GGRAPHS, 512>>>(hA, batch);
    k_mlp<<<GGRAPHS, 64>>>(Wl1, bl1, Wl2, bl2, out);
}

// round 8
// speedup vs baseline: 1.4856x; 1.4856x over previous
#include <cuda_runtime.h>
#include <cuda_bf16.h>
#include <math.h>

#define N_NODES 100000
#define E_EDGES 1600000
#define FDIM    128
#define GGRAPHS 64
#define COUT    10
#define SCAN_B  ((N_NODES + 255) / 256)   // 391

// -------------------- scratch (static device globals) -----------------------
__device__ int   g_deg[N_NODES];
__device__ int   g_rowptr[N_NODES + 1];
__device__ int   g_cursor[N_NODES];
__device__ int   g_csr[E_EDGES];
__device__ int   g_bsum[SCAN_B];
__device__ int   g_boff[SCAN_B];
// W split planes, layout [layer][ktile 8][row 256][16 permuted]
__device__ __align__(16) __nv_bfloat16 g_whi[3 * 256 * FDIM];
__device__ __align__(16) __nv_bfloat16 g_wlo[3 * 256 * FDIM];
__device__ float g_xr[(size_t)N_NODES * FDIM];
__device__ float g_xo[(size_t)N_NODES * FDIM];
__device__ float g_hA[(size_t)N_NODES * FDIM];
__device__ float g_hB[(size_t)N_NODES * FDIM];
__device__ float g_pooled[GGRAPHS * FDIM];

// -------------------- CSR build ---------------------------------------------
__global__ void k_zero_deg() {
    int i = blockIdx.x * blockDim.x + threadIdx.x;
    if (i < N_NODES) g_deg[i] = 0;
}

__global__ void k_hist(const int* __restrict__ ei) {
    int e = blockIdx.x * blockDim.x + threadIdx.x;
    if (e < E_EDGES) atomicAdd(&g_deg[ei[E_EDGES + e]], 1);
}

__global__ void k_scan1() {
    __shared__ int sh[256];
    int tid = threadIdx.x;
    int i = blockIdx.x * 256 + tid;
    int v = (i < N_NODES) ? g_deg[i] : 0;
    sh[tid] = v;
    __syncthreads();
    for (int d = 128; d > 0; d >>= 1) {
        if (tid < d) sh[tid] += sh[tid + d];
        __syncthreads();
    }
    if (tid == 0) g_bsum[blockIdx.x] = sh[0];
}

__global__ void k_scan2() {
    __shared__ int s[512];
    int tid = threadIdx.x;
    int v = (tid < SCAN_B) ? g_bsum[tid] : 0;
    s[tid] = v;
    __syncthreads();
    for (int d = 1; d < 512; d <<= 1) {
        int t = (tid >= d) ? s[tid - d] : 0;
        __syncthreads();
        s[tid] += t;
        __syncthreads();
    }
    if (tid < SCAN_B) g_boff[tid] = s[tid] - v;
}

__global__ void k_scan3() {
    __shared__ int s[256];
    int tid = threadIdx.x;
    int i = blockIdx.x * 256 + tid;
    int v = (i < N_NODES) ? g_deg[i] : 0;
    s[tid] = v;
    __syncthreads();
    for (int d = 1; d < 256; d <<= 1) {
        int t = (tid >= d) ? s[tid - d] : 0;
        __syncthreads();
        s[tid] += t;
        __syncthreads();
    }
    int excl = s[tid] - v + g_boff[blockIdx.x];
    if (i < N_NODES) {
        g_rowptr[i] = excl;
        g_cursor[i] = excl;
        if (i == N_NODES - 1) g_rowptr[N_NODES] = excl + v;
    }
}

__global__ void k_fill(const int* __restrict__ ei) {
    int e = blockIdx.x * blockDim.x + threadIdx.x;
    if (e < E_EDGES) {
        int d = ei[E_EDGES + e];
        int p = atomicAdd(&g_cursor[d], 1);
        g_csr[p] = ei[e];
    }
}

// -------------------- W split planes (tile-major, k-permuted) ---------------
__global__ void k_split_w(const float* __restrict__ Wr,
                          const float* __restrict__ Wo, int layer) {
    int row = blockIdx.x;           // 0..255 (0-127 Wr, 128-255 Wo)
    int k = threadIdx.x;            // 0..127
    const float* src = (row < 128) ? (Wr + (size_t)row * FDIM)
                                   : (Wo + (size_t)(row - 128) * FDIM);
    float v = src[k];
    __nv_bfloat16 h = __float2bfloat16(v);
    __nv_bfloat16 l = __float2bfloat16(v - __bfloat162float(h));
    int tile = k >> 4, kk = k & 15;
    int p = 4 * ((kk & 7) >> 1) + 2 * ((kk >> 3) & 1) + (kk & 1);
    int idx = layer * 256 * FDIM + tile * 4096 + row * 16 + p;
    g_whi[idx] = h;
    g_wlo[idx] = l;
}

// ===================== dual bf16-split GEMM =================================
// xr = A @ Wr^T, xo = A @ Wo^T.  A fp32 (split at staging), W planes
// precomputed. Tile M=64, 8 warps: warp = 16 rows x 128 cols of R or O.
__device__ __forceinline__ void mma16(float* c, const unsigned* a,
                                      unsigned b0, unsigned b1) {
    asm volatile(
        "mma.sync.aligned.m16n8k16.row.col.f32.bf16.bf16.f32 "
        "{%0,%1,%2,%3},{%4,%5,%6,%7},{%8,%9},{%0,%1,%2,%3};"
        : "+f"(c[0]), "+f"(c[1]), "+f"(c[2]), "+f"(c[3])
        : "r"(a[0]), "r"(a[1]), "r"(a[2]), "r"(a[3]), "r"(b0), "r"(b1));
}

__global__ __launch_bounds__(256, 2) void k_gemm_dual(
    const float* __restrict__ A, int layer, int M)
{
    __shared__ __align__(16) __nv_bfloat16 sAh[2][64 * 16];
    __shared__ __align__(16) __nv_bfloat16 sAl[2][64 * 16];
    __shared__ __align__(16) __nv_bfloat16 sBh[2][256 * 16];
    __shared__ __align__(16) __nv_bfloat16 sBl[2][256 * 16];

    int tid = threadIdx.x;
    int m0 = blockIdx.x * 64;
    int warp = tid >> 5, lane = tid & 31;
    int wm = warp >> 1;          // 0..3 -> 16-row slice
    int sel = warp & 1;          // 0: Wr -> xr, 1: Wo -> xo
    int gq = lane >> 2, t4 = lane & 3;

    const __nv_bfloat16* Whi = g_whi + layer * 256 * FDIM;
    const __nv_bfloat16* Wlo = g_wlo + layer * 256 * FDIM;

    // A staging: thread -> row ar=tid>>2, float4 chunk c=tid&3 (16 k)
    int ar = tid >> 2, ac = tid & 3;
    bool aok = (m0 + ar) < M;
    const float4* aptr = (const float4*)(A + (size_t)(m0 + ar) * FDIM) + ac;
    int pb = (ac & 1) * 8 + (ac >> 1) * 2;   // permuted pair base

    // W staging: chunk f = tid + i*256 -> row f>>1, 8-elem half f&1 (x2 planes)
    int wr0 = tid >> 1, wc0 = (tid & 1) * 8;
    int wr1 = (tid + 256) >> 1, wc1 = ((tid + 256) & 1) * 8;

    float4 va; uint4 wh0, wh1, wl0, wl1;
#define LOADI(i) do {                                                          \
        va  = aok ? __ldg(aptr + (i) * 4) : make_float4(0.f, 0.f, 0.f, 0.f);   \
        const __nv_bfloat16* sl = Whi + (i) * 4096;                            \
        const __nv_bfloat16* s2 = Wlo + (i) * 4096;                            \
        wh0 = *(const uint4*)(sl + wr0 * 16 + wc0);                            \
        wh1 = *(const uint4*)(sl + wr1 * 16 + wc1);                            \
        wl0 = *(const uint4*)(s2 + wr0 * 16 + wc0);                            \
        wl1 = *(const uint4*)(s2 + wr1 * 16 + wc1);                            \
    } while (0)

#define STOREI(b) do {                                                         \
        __nv_bfloat162 h1 = __floats2bfloat162_rn(va.x, va.y);                 \
        __nv_bfloat162 h2 = __floats2bfloat162_rn(va.z, va.w);                 \
        float ex = va.x - __bfloat162float(__low2bfloat16(h1));                \
        float ey = va.y - __bfloat162float(__high2bfloat16(h1));               \
        float ez = va.z - __bfloat162float(__low2bfloat16(h2));                \
        float ew = va.w - __bfloat162float(__high2bfloat16(h2));               \
        __nv_bfloat162 l1 = __floats2bfloat162_rn(ex, ey);                     \
        __nv_bfloat162 l2 = __floats2bfloat162_rn(ez, ew);                     \
        *(unsigned*)(sAh[b] + ar * 16 + pb)     = *(unsigned*)&h1;             \
        *(unsigned*)(sAh[b] + ar * 16 + pb + 4) = *(unsigned*)&h2;             \
        *(unsigned*)(sAl[b] + ar * 16 + pb)     = *(unsigned*)&l1;             \
        *(unsigned*)(sAl[b] + ar * 16 + pb + 4) = *(unsigned*)&l2;             \
        *(uint4*)(sBh[b] + wr0 * 16 + wc0) = wh0;                              \
        *(uint4*)(sBh[b] + wr1 * 16 + wc1) = wh1;                              \
        *(uint4*)(sBl[b] + wr0 * 16 + wc0) = wl0;                              \
        *(uint4*)(sBl[b] + wr1 * 16 + wc1) = wl1;                              \
    } while (0)

    float acc[16][4];
#pragma unroll
    for (int j = 0; j < 16; j++)
#pragma unroll
        for (int q = 0; q < 4; q++) acc[j][q] = 0.f;

    LOADI(0);
    STOREI(0);
    __syncthreads();

#pragma unroll
    for (int it = 0; it < 8; it++) {
        int cur = it & 1;
        if (it < 7) {
            LOADI(it + 1);
            STOREI(1 - cur);
        }
        // A fragments (rows wm*16+gq, +8), one LDS.64 per plane per row
        int r1 = wm * 16 + gq;
        uint2 v1 = *(const uint2*)(sAh[cur] + r1 * 16 + 4 * t4);
        uint2 v2 = *(const uint2*)(sAh[cur] + (r1 + 8) * 16 + 4 * t4);
        uint2 w1 = *(const uint2*)(sAl[cur] + r1 * 16 + 4 * t4);
        uint2 w2 = *(const uint2*)(sAl[cur] + (r1 + 8) * 16 + 4 * t4);
        unsigned ah[4] = {v1.x, v2.x, v1.y, v2.y};
        unsigned al[4] = {w1.x, w2.x, w1.y, w2.y};
#pragma unroll
        for (int nt = 0; nt < 16; nt++) {
            int n = sel * 128 + nt * 8 + gq;
            uint2 bh = *(const uint2*)(sBh[cur] + n * 16 + 4 * t4);
            uint2 bl = *(const uint2*)(sBl[cur] + n * 16 + 4 * t4);
            mma16(acc[nt], al, bh.x, bh.y);
            mma16(acc[nt], ah, bl.x, bl.y);
            mma16(acc[nt], ah, bh.x, bh.y);
        }
        __syncthreads();
    }
#undef LOADI
#undef STOREI

    float* dst = sel ? g_xo : g_xr;
    int r0 = m0 + wm * 16 + gq;
#pragma unroll
    for (int nt = 0; nt < 16; nt++) {
        int cc = nt * 8 + t4 * 2;
        if (r0 < M) {
            float2 o; o.x = acc[nt][0]; o.y = acc[nt][1];
            *(float2*)(dst + (size_t)r0 * FDIM + cc) = o;
        }
        if (r0 + 8 < M) {
            float2 o; o.x = acc[nt][2]; o.y = acc[nt][3];
            *(float2*)(dst + (size_t)(r0 + 8) * FDIM + cc) = o;
        }
    }
}

// ----- fused: out_i = relu( sum_{j->i} xr[j] + xo[i] + bias ) ---------------
__global__ void k_agg(const float* __restrict__ xr,
                      const float* __restrict__ xo,
                      const float* __restrict__ bias,
                      float* __restrict__ out)
{
    int node = (blockIdx.x * blockDim.x + threadIdx.x) >> 5;
    if (node >= N_NODES) return;
    int lane = threadIdx.x & 31;
    int beg = g_rowptr[node];
    int end = g_rowptr[node + 1];
    float4 a0 = make_float4(0.f, 0.f, 0.f, 0.f);
    float4 a1 = make_float4(0.f, 0.f, 0.f, 0.f);
    int e = beg;
    for (; e + 4 <= end; e += 4) {
        int s0 = g_csr[e], s1 = g_csr[e + 1], s2 = g_csr[e + 2], s3 = g_csr[e + 3];
        float4 v0 = __ldg((const float4*)(xr + (size_t)s0 * FDIM) + lane);
        float4 v1 = __ldg((const float4*)(xr + (size_t)s1 * FDIM) + lane);
        float4 v2 = __ldg((const float4*)(xr + (size_t)s2 * FDIM) + lane);
        float4 v3 = __ldg((const float4*)(xr + (size_t)s3 * FDIM) + lane);
        a0.x += v0.x + v1.x; a0.y += v0.y + v1.y;
        a0.z += v0.z + v1.z; a0.w += v0.w + v1.w;
        a1.x += v2.x + v3.x; a1.y += v2.y + v3.y;
        a1.z += v2.z + v3.z; a1.w += v2.w + v3.w;
    }
    for (; e < end; e++) {
        int s0 = g_csr[e];
        float4 v0 = __ldg((const float4*)(xr + (size_t)s0 * FDIM) + lane);
        a0.x += v0.x; a0.y += v0.y; a0.z += v0.z; a0.w += v0.w;
    }
    float4 o = __ldg((const float4*)(xo + (size_t)node * FDIM) + lane);
    float4 b = __ldg((const float4*)bias + lane);
    float4 r;
    r.x = fmaxf(a0.x + a1.x + o.x + b.x, 0.f);
    r.y = fmaxf(a0.y + a1.y + o.y + b.y, 0.f);
    r.z = fmaxf(a0.z + a1.z + o.z + b.z, 0.f);
    r.w = fmaxf(a0.w + a1.w + o.w + b.w, 0.f);
    ((float4*)(out + (size_t)node * FDIM))[lane] = r;
}

// -------------------- mean pool (sorted batch ids, 4 row-stripes) -----------
__global__ void k_pool(const float* __restrict__ h, const int* __restrict__ batch) {
    int g = blockIdx.x;
    int t = threadIdx.x;                 // 0..511
    int col = t & 127, stripe = t >> 7;
    int lo, hi;
    {
        int key = g;
        int a = 0, b = N_NODES;
        while (a < b) { int m = (a + b) >> 1; if (batch[m] < key) a = m + 1; else b = m; }
        lo = a;
        key = g + 1; a = lo; b = N_NODES;
        while (a < b) { int m = (a + b) >> 1; if (batch[m] < key) a = m + 1; else b = m; }
        hi = a;
    }
    float s = 0.f;
    for (int n = lo + stripe; n < hi; n += 4) s += h[(size_t)n * FDIM + col];
    __shared__ float red[4][FDIM];
    red[stripe][col] = s;
    __syncthreads();
    if (stripe == 0) {
        float tot = red[0][col] + red[1][col] + red[2][col] + red[3][col];
        float c = (float)max(hi - lo, 1);
        g_pooled[g * FDIM + col] = tot / c;
    }
}

// -------------------- MLP head + log_softmax --------------------------------
__global__ void k_mlp(const float* __restrict__ Wl1, const float* __restrict__ bl1,
                      const float* __restrict__ Wl2, const float* __restrict__ bl2,
                      float* __restrict__ out)
{
    int g = blockIdx.x;
    int t = threadIdx.x;
    __shared__ float p[FDIM];
    __shared__ float h1[64];
    __shared__ float lg[COUT];
    p[t]      = g_pooled[g * FDIM + t];
    p[t + 64] = g_pooled[g * FDIM + 64 + t];
    __syncthreads();
    float s = bl1[t];
#pragma unroll 8
    for (int k = 0; k < FDIM; k++) s += p[k] * Wl1[t * FDIM + k];
    h1[t] = fmaxf(s, 0.f);
    __syncthreads();
    if (t < COUT) {
        float s2 = bl2[t];
#pragma unroll 8
        for (int k = 0; k < 64; k++) s2 += h1[k] * Wl2[t * 64 + k];
        lg[t] = s2;
    }
    __syncthreads();
    if (t == 0) {
        float mx = -INFINITY;
        for (int c = 0; c < COUT; c++) mx = fmaxf(mx, lg[c]);
        float se = 0.f;
        for (int c = 0; c < COUT; c++) se += expf(lg[c] - mx);
        float lse = logf(se) + mx;
        for (int c = 0; c < COUT; c++) out[g * COUT + c] = lg[c] - lse;
    }
}

// -------------------- launch ------------------------------------------------
extern "C" void kernel_launch(void* const* d_in, const int* in_sizes, int n_in,
                              void* d_out, int out_size)
{
    const float* x     = (const float*)d_in[0];
    const int*   ei    = (const int*)d_in[1];
    const int*   batch = (const int*)d_in[2];
    int wb = 3;
    if (n_in > 3 && in_sizes[3] <= 4) wb = 4;
    const float* W1r = (const float*)d_in[wb + 0];
    const float* b1  = (const float*)d_in[wb + 1];
    const float* W1o = (const float*)d_in[wb + 2];
    const float* W2r = (const float*)d_in[wb + 3];
    const float* b2  = (const float*)d_in[wb + 4];
    const float* W2o = (const float*)d_in[wb + 5];
    const float* W3r = (const float*)d_in[wb + 6];
    const float* b3  = (const float*)d_in[wb + 7];
    const float* W3o = (const float*)d_in[wb + 8];
    const float* Wl1 = (const float*)d_in[wb + 9];
    const float* bl1 = (const float*)d_in[wb + 10];
    const float* Wl2 = (const float*)d_in[wb + 11];
    const float* bl2 = (const float*)d_in[wb + 12];
    float* out = (float*)d_out;

    float *xr, *xo, *hA, *hB;
    cudaGetSymbolAddress((void**)&xr, g_xr);
    cudaGetSymbolAddress((void**)&xo, g_xo);
    cudaGetSymbolAddress((void**)&hA, g_hA);
    cudaGetSymbolAddress((void**)&hB, g_hB);

    // W split planes (once)
    k_split_w<<<256, 128>>>(W1r, W1o, 0);
    k_split_w<<<256, 128>>>(W2r, W2o, 1);
    k_split_w<<<256, 128>>>(W3r, W3o, 2);

    // CSR build
    k_zero_deg<<<(N_NODES + 255) / 256, 256>>>();
    k_hist<<<(E_EDGES + 255) / 256, 256>>>(ei);
    k_scan1<<<SCAN_B, 256>>>();
    k_scan2<<<1, 512>>>();
    k_scan3<<<SCAN_B, 256>>>();
    k_fill<<<(E_EDGES + 255) / 256, 256>>>(ei);

    int gemmBlocks = (N_NODES + 63) / 64;
    int aggBlocks  = (N_NODES * 32 + 255) / 256;

    // layer 1
    k_gemm_dual<<<gemmBlocks, 256>>>(x, 0, N_NODES);
    k_agg<<<aggBlocks, 256>>>(xr, xo, b1, hA);
    // layer 2
    k_gemm_dual<<<gemmBlocks, 256>>>(hA, 1, N_NODES);
    k_agg<<<aggBlocks, 256>>>(xr, xo, b2, hB);
    // layer 3
    k_gemm_dual<<<gemmBlocks, 256>>>(hB, 2, N_NODES);
    k_agg<<<aggBlocks, 256>>>(xr, xo, b3, hA);

    // pool + head
    k_pool<<<GGRAPHS, 512>>>(hA, batch);
    k_mlp<<<GGRAPHS, 64>>>(Wl1, bl1, Wl2, bl2, out);
}

// round 9
// speedup vs baseline: 1.6883x; 1.1364x over previous
#include <cuda_runtime.h>
#include <cuda_bf16.h>
#include <cuda_fp16.h>
#include <math.h>

#define N_NODES 100000
#define E_EDGES 1600000
#define FDIM    128
#define GGRAPHS 64
#define COUT    10
#define SCAN_B  ((N_NODES + 255) / 256)   // 391

// -------------------- scratch (static device globals) -----------------------
__device__ int   g_deg[N_NODES];
__device__ int   g_rowptr[N_NODES + 1];
__device__ int   g_cursor[N_NODES];
__device__ int   g_csr[E_EDGES];
__device__ int   g_bsum[SCAN_B];
__device__ int   g_boff[SCAN_B];
// W split planes, layout [layer][ktile 8][row 256][16 permuted]
__device__ __align__(16) __nv_bfloat16 g_whi[3 * 256 * FDIM];
__device__ __align__(16) __nv_bfloat16 g_wlo[3 * 256 * FDIM];
__device__ __align__(16) __half g_xrh[(size_t)N_NODES * FDIM];  // fp16 gather payload
__device__ float g_xo[(size_t)N_NODES * FDIM];
__device__ float g_hA[(size_t)N_NODES * FDIM];
__device__ float g_hB[(size_t)N_NODES * FDIM];
__device__ float g_pooled[GGRAPHS * FDIM];

// -------------------- CSR build ---------------------------------------------
__global__ void k_zero_deg() {
    int i = blockIdx.x * blockDim.x + threadIdx.x;
    if (i < N_NODES) g_deg[i] = 0;
}

__global__ void k_hist(const int* __restrict__ ei) {
    int e = blockIdx.x * blockDim.x + threadIdx.x;
    if (e < E_EDGES) atomicAdd(&g_deg[ei[E_EDGES + e]], 1);
}

__global__ void k_scan1() {
    __shared__ int sh[256];
    int tid = threadIdx.x;
    int i = blockIdx.x * 256 + tid;
    int v = (i < N_NODES) ? g_deg[i] : 0;
    sh[tid] = v;
    __syncthreads();
    for (int d = 128; d > 0; d >>= 1) {
        if (tid < d) sh[tid] += sh[tid + d];
        __syncthreads();
    }
    if (tid == 0) g_bsum[blockIdx.x] = sh[0];
}

__global__ void k_scan2() {
    __shared__ int s[512];
    int tid = threadIdx.x;
    int v = (tid < SCAN_B) ? g_bsum[tid] : 0;
    s[tid] = v;
    __syncthreads();
    for (int d = 1; d < 512; d <<= 1) {
        int t = (tid >= d) ? s[tid - d] : 0;
        __syncthreads();
        s[tid] += t;
        __syncthreads();
    }
    if (tid < SCAN_B) g_boff[tid] = s[tid] - v;
}

__global__ void k_scan3() {
    __shared__ int s[256];
    int tid = threadIdx.x;
    int i = blockIdx.x * 256 + tid;
    int v = (i < N_NODES) ? g_deg[i] : 0;
    s[tid] = v;
    __syncthreads();
    for (int d = 1; d < 256; d <<= 1) {
        int t = (tid >= d) ? s[tid - d] : 0;
        __syncthreads();
        s[tid] += t;
        __syncthreads();
    }
    int excl = s[tid] - v + g_boff[blockIdx.x];
    if (i < N_NODES) {
        g_rowptr[i] = excl;
        g_cursor[i] = excl;
        if (i == N_NODES - 1) g_rowptr[N_NODES] = excl + v;
    }
}

__global__ void k_fill(const int* __restrict__ ei) {
    int e = blockIdx.x * blockDim.x + threadIdx.x;
    if (e < E_EDGES) {
        int d = ei[E_EDGES + e];
        int p = atomicAdd(&g_cursor[d], 1);
        g_csr[p] = ei[e];
    }
}

// -------------------- W split planes (tile-major, k-permuted) ---------------
__global__ void k_split_w(const float* __restrict__ Wr,
                          const float* __restrict__ Wo, int layer) {
    int row = blockIdx.x;           // 0..255 (0-127 Wr, 128-255 Wo)
    int k = threadIdx.x;            // 0..127
    const float* src = (row < 128) ? (Wr + (size_t)row * FDIM)
                                   : (Wo + (size_t)(row - 128) * FDIM);
    float v = src[k];
    __nv_bfloat16 h = __float2bfloat16(v);
    __nv_bfloat16 l = __float2bfloat16(v - __bfloat162float(h));
    int tile = k >> 4, kk = k & 15;
    int p = 4 * ((kk & 7) >> 1) + 2 * ((kk >> 3) & 1) + (kk & 1);
    int idx = layer * 256 * FDIM + tile * 4096 + row * 16 + p;
    g_whi[idx] = h;
    g_wlo[idx] = l;
}

// ===================== dual bf16-split GEMM =================================
// sel=0 warps: xr = A @ Wr^T  -> fp16 g_xrh.  sel=1: xo = A @ Wo^T -> fp32.
__device__ __forceinline__ void mma16(float* c, const unsigned* a,
                                      unsigned b0, unsigned b1) {
    asm volatile(
        "mma.sync.aligned.m16n8k16.row.col.f32.bf16.bf16.f32 "
        "{%0,%1,%2,%3},{%4,%5,%6,%7},{%8,%9},{%0,%1,%2,%3};"
        : "+f"(c[0]), "+f"(c[1]), "+f"(c[2]), "+f"(c[3])
        : "r"(a[0]), "r"(a[1]), "r"(a[2]), "r"(a[3]), "r"(b0), "r"(b1));
}

__global__ __launch_bounds__(256, 2) void k_gemm_dual(
    const float* __restrict__ A, int layer, int M)
{
    __shared__ __align__(16) __nv_bfloat16 sAh[2][64 * 16];
    __shared__ __align__(16) __nv_bfloat16 sAl[2][64 * 16];
    __shared__ __align__(16) __nv_bfloat16 sBh[2][256 * 16];
    __shared__ __align__(16) __nv_bfloat16 sBl[2][256 * 16];

    int tid = threadIdx.x;
    int m0 = blockIdx.x * 64;
    int warp = tid >> 5, lane = tid & 31;
    int wm = warp >> 1;          // 0..3 -> 16-row slice
    int sel = warp & 1;          // 0: Wr -> xrh(fp16), 1: Wo -> xo(fp32)
    int gq = lane >> 2, t4 = lane & 3;

    const __nv_bfloat16* Whi = g_whi + layer * 256 * FDIM;
    const __nv_bfloat16* Wlo = g_wlo + layer * 256 * FDIM;

    int ar = tid >> 2, ac = tid & 3;
    bool aok = (m0 + ar) < M;
    const float4* aptr = (const float4*)(A + (size_t)(m0 + ar) * FDIM) + ac;
    int pb = (ac & 1) * 8 + (ac >> 1) * 2;

    int wr0 = tid >> 1, wc0 = (tid & 1) * 8;
    int wr1 = (tid + 256) >> 1, wc1 = ((tid + 256) & 1) * 8;

    float4 va; uint4 wh0, wh1, wl0, wl1;
#define LOADI(i) do {                                                          \
        va  = aok ? __ldg(aptr + (i) * 4) : make_float4(0.f, 0.f, 0.f, 0.f);   \
        const __nv_bfloat16* sl = Whi + (i) * 4096;                            \
        const __nv_bfloat16* s2 = Wlo + (i) * 4096;                            \
        wh0 = *(const uint4*)(sl + wr0 * 16 + wc0);                            \
        wh1 = *(const uint4*)(sl + wr1 * 16 + wc1);                            \
        wl0 = *(const uint4*)(s2 + wr0 * 16 + wc0);                            \
        wl1 = *(const uint4*)(s2 + wr1 * 16 + wc1);                            \
    } while (0)

#define STOREI(b) do {                                                         \
        __nv_bfloat162 h1 = __floats2bfloat162_rn(va.x, va.y);                 \
        __nv_bfloat162 h2 = __floats2bfloat162_rn(va.z, va.w);                 \
        float ex = va.x - __bfloat162float(__low2bfloat16(h1));                \
        float ey = va.y - __bfloat162float(__high2bfloat16(h1));               \
        float ez = va.z - __bfloat162float(__low2bfloat16(h2));                \
        float ew = va.w - __bfloat162float(__high2bfloat16(h2));               \
        __nv_bfloat162 l1 = __floats2bfloat162_rn(ex, ey);                     \
        __nv_bfloat162 l2 = __floats2bfloat162_rn(ez, ew);                     \
        *(unsigned*)(sAh[b] + ar * 16 + pb)     = *(unsigned*)&h1;             \
        *(unsigned*)(sAh[b] + ar * 16 + pb + 4) = *(unsigned*)&h2;             \
        *(unsigned*)(sAl[b] + ar * 16 + pb)     = *(unsigned*)&l1;             \
        *(unsigned*)(sAl[b] + ar * 16 + pb + 4) = *(unsigned*)&l2;             \
        *(uint4*)(sBh[b] + wr0 * 16 + wc0) = wh0;                              \
        *(uint4*)(sBh[b] + wr1 * 16 + wc1) = wh1;                              \
        *(uint4*)(sBl[b] + wr0 * 16 + wc0) = wl0;                              \
        *(uint4*)(sBl[b] + wr1 * 16 + wc1) = wl1;                              \
    } while (0)

    float acc[16][4];
#pragma unroll
    for (int j = 0; j < 16; j++)
#pragma unroll
        for (int q = 0; q < 4; q++) acc[j][q] = 0.f;

    LOADI(0);
    STOREI(0);
    __syncthreads();

#pragma unroll
    for (int it = 0; it < 8; it++) {
        int cur = it & 1;
        if (it < 7) {
            LOADI(it + 1);
            STOREI(1 - cur);
        }
        int r1 = wm * 16 + gq;
        uint2 v1 = *(const uint2*)(sAh[cur] + r1 * 16 + 4 * t4);
        uint2 v2 = *(const uint2*)(sAh[cur] + (r1 + 8) * 16 + 4 * t4);
        uint2 w1 = *(const uint2*)(sAl[cur] + r1 * 16 + 4 * t4);
        uint2 w2 = *(const uint2*)(sAl[cur] + (r1 + 8) * 16 + 4 * t4);
        unsigned ah[4] = {v1.x, v2.x, v1.y, v2.y};
        unsigned al[4] = {w1.x, w2.x, w1.y, w2.y};
#pragma unroll
        for (int nt = 0; nt < 16; nt++) {
            int n = sel * 128 + nt * 8 + gq;
            uint2 bh = *(const uint2*)(sBh[cur] + n * 16 + 4 * t4);
            uint2 bl = *(const uint2*)(sBl[cur] + n * 16 + 4 * t4);
            mma16(acc[nt], al, bh.x, bh.y);
            mma16(acc[nt], ah, bl.x, bl.y);
            mma16(acc[nt], ah, bh.x, bh.y);
        }
        __syncthreads();
    }
#undef LOADI
#undef STOREI

    int r0 = m0 + wm * 16 + gq;
    if (sel == 0) {
        // fp16 stores to gather payload
#pragma unroll
        for (int nt = 0; nt < 16; nt++) {
            int cc = nt * 8 + t4 * 2;
            if (r0 < M)
                *(__half2*)(g_xrh + (size_t)r0 * FDIM + cc) =
                    __floats2half2_rn(acc[nt][0], acc[nt][1]);
            if (r0 + 8 < M)
                *(__half2*)(g_xrh + (size_t)(r0 + 8) * FDIM + cc) =
                    __floats2half2_rn(acc[nt][2], acc[nt][3]);
        }
    } else {
#pragma unroll
        for (int nt = 0; nt < 16; nt++) {
            int cc = nt * 8 + t4 * 2;
            if (r0 < M) {
                float2 o; o.x = acc[nt][0]; o.y = acc[nt][1];
                *(float2*)(g_xo + (size_t)r0 * FDIM + cc) = o;
            }
            if (r0 + 8 < M) {
                float2 o; o.x = acc[nt][2]; o.y = acc[nt][3];
                *(float2*)(g_xo + (size_t)(r0 + 8) * FDIM + cc) = o;
            }
        }
    }
}

// ----- fused: out_i = relu( sum_{j->i} xrh[j] + xo[i] + bias ) --------------
__global__ void k_agg(const float* __restrict__ xo,
                      const float* __restrict__ bias,
                      float* __restrict__ out)
{
    int node = (blockIdx.x * blockDim.x + threadIdx.x) >> 5;
    if (node >= N_NODES) return;
    int lane = threadIdx.x & 31;
    int beg = g_rowptr[node];
    int end = g_rowptr[node + 1];
    const __half* xr = g_xrh;
    float4 a0 = make_float4(0.f, 0.f, 0.f, 0.f);
    float4 a1 = make_float4(0.f, 0.f, 0.f, 0.f);
    int e = beg;
#define GATH(acc, s) do {                                                    \
        uint2 raw = __ldg((const uint2*)(xr + (size_t)(s) * FDIM) + lane);   \
        float2 f0 = __half22float2(*(__half2*)&raw.x);                       \
        float2 f1 = __half22float2(*(__half2*)&raw.y);                       \
        acc.x += f0.x; acc.y += f0.y; acc.z += f1.x; acc.w += f1.y;          \
    } while (0)
    for (; e + 4 <= end; e += 4) {
        int s0 = g_csr[e], s1 = g_csr[e + 1], s2 = g_csr[e + 2], s3 = g_csr[e + 3];
        GATH(a0, s0); GATH(a1, s1); GATH(a0, s2); GATH(a1, s3);
    }
    for (; e < end; e++) {
        int s0 = g_csr[e];
        GATH(a0, s0);
    }
#undef GATH
    float4 o = __ldg((const float4*)(xo + (size_t)node * FDIM) + lane);
    float4 b = __ldg((const float4*)bias + lane);
    float4 r;
    r.x = fmaxf(a0.x + a1.x + o.x + b.x, 0.f);
    r.y = fmaxf(a0.y + a1.y + o.y + b.y, 0.f);
    r.z = fmaxf(a0.z + a1.z + o.z + b.z, 0.f);
    r.w = fmaxf(a0.w + a1.w + o.w + b.w, 0.f);
    ((float4*)(out + (size_t)node * FDIM))[lane] = r;
}

// -------------------- mean pool (sorted batch ids, 4 row-stripes) -----------
__global__ void k_pool(const float* __restrict__ h, const int* __restrict__ batch) {
    int g = blockIdx.x;
    int t = threadIdx.x;                 // 0..511
    int col = t & 127, stripe = t >> 7;
    int lo, hi;
    {
        int key = g;
        int a = 0, b = N_NODES;
        while (a < b) { int m = (a + b) >> 1; if (batch[m] < key) a = m + 1; else b = m; }
        lo = a;
        key = g + 1; a = lo; b = N_NODES;
        while (a < b) { int m = (a + b) >> 1; if (batch[m] < key) a = m + 1; else b = m; }
        hi = a;
    }
    float s = 0.f;
    for (int n = lo + stripe; n < hi; n += 4) s += h[(size_t)n * FDIM + col];
    __shared__ float red[4][FDIM];
    red[stripe][col] = s;
    __syncthreads();
    if (stripe == 0) {
        float tot = red[0][col] + red[1][col] + red[2][col] + red[3][col];
        float c = (float)max(hi - lo, 1);
        g_pooled[g * FDIM + col] = tot / c;
    }
}

// -------------------- MLP head + log_softmax --------------------------------
__global__ void k_mlp(const float* __restrict__ Wl1, const float* __restrict__ bl1,
                      const float* __restrict__ Wl2, const float* __restrict__ bl2,
                      float* __restrict__ out)
{
    int g = blockIdx.x;
    int t = threadIdx.x;
    __shared__ float p[FDIM];
    __shared__ float h1[64];
    __shared__ float lg[COUT];
    p[t]      = g_pooled[g * FDIM + t];
    p[t + 64] = g_pooled[g * FDIM + 64 + t];
    __syncthreads();
    float s = bl1[t];
#pragma unroll 8
    for (int k = 0; k < FDIM; k++) s += p[k] * Wl1[t * FDIM + k];
    h1[t] = fmaxf(s, 0.f);
    __syncthreads();
    if (t < COUT) {
        float s2 = bl2[t];
#pragma unroll 8
        for (int k = 0; k < 64; k++) s2 += h1[k] * Wl2[t * 64 + k];
        lg[t] = s2;
    }
    __syncthreads();
    if (t == 0) {
        float mx = -INFINITY;
        for (int c = 0; c < COUT; c++) mx = fmaxf(mx, lg[c]);
        float se = 0.f;
        for (int c = 0; c < COUT; c++) se += expf(lg[c] - mx);
        float lse = logf(se) + mx;
        for (int c = 0; c < COUT; c++) out[g * COUT + c] = lg[c] - lse;
    }
}

// -------------------- launch ------------------------------------------------
extern "C" void kernel_launch(void* const* d_in, const int* in_sizes, int n_in,
                              void* d_out, int out_size)
{
    const float* x     = (const float*)d_in[0];
    const int*   ei    = (const int*)d_in[1];
    const int*   batch = (const int*)d_in[2];
    int wb = 3;
    if (n_in > 3 && in_sizes[3] <= 4) wb = 4;
    const float* W1r = (const float*)d_in[wb + 0];
    const float* b1  = (const float*)d_in[wb + 1];
    const float* W1o = (const float*)d_in[wb + 2];
    const float* W2r = (const float*)d_in[wb + 3];
    const float* b2  = (const float*)d_in[wb + 4];
    const float* W2o = (const float*)d_in[wb + 5];
    const float* W3r = (const float*)d_in[wb + 6];
    const float* b3  = (const float*)d_in[wb + 7];
    const float* W3o = (const float*)d_in[wb + 8];
    const float* Wl1 = (const float*)d_in[wb + 9];
    const float* bl1 = (const float*)d_in[wb + 10];
    const float* Wl2 = (const float*)d_in[wb + 11];
    const float* bl2 = (const float*)d_in[wb + 12];
    float* out = (float*)d_out;

    float *xo, *hA, *hB;
    cudaGetSymbolAddress((void**)&xo, g_xo);
    cudaGetSymbolAddress((void**)&hA, g_hA);
    cudaGetSymbolAddress((void**)&hB, g_hB);

    // W split planes (once)
    k_split_w<<<256, 128>>>(W1r, W1o, 0);
    k_split_w<<<256, 128>>>(W2r, W2o, 1);
    k_split_w<<<256, 128>>>(W3r, W3o, 2);

    // CSR build
    k_zero_deg<<<(N_NODES + 255) / 256, 256>>>();
    k_hist<<<(E_EDGES + 255) / 256, 256>>>(ei);
    k_scan1<<<SCAN_B, 256>>>();
    k_scan2<<<1, 512>>>();
    k_scan3<<<SCAN_B, 256>>>();
    k_fill<<<(E_EDGES + 255) / 256, 256>>>(ei);

    int gemmBlocks = (N_NODES + 63) / 64;
    int aggBlocks  = (N_NODES * 32 + 255) / 256;

    // layer 1
    k_gemm_dual<<<gemmBlocks, 256>>>(x, 0, N_NODES);
    k_agg<<<aggBlocks, 256>>>(xo, b1, hA);
    // layer 2
    k_gemm_dual<<<gemmBlocks, 256>>>(hA, 1, N_NODES);
    k_agg<<<aggBlocks, 256>>>(xo, b2, hB);
    // layer 3
    k_gemm_dual<<<gemmBlocks, 256>>>(hB, 2, N_NODES);
    k_agg<<<aggBlocks, 256>>>(xo, b3, hA);

    // pool + head
    k_pool<<<GGRAPHS, 512>>>(hA, batch);
    k_mlp<<<GGRAPHS, 64>>>(Wl1, bl1, Wl2, bl2, out);
}

// round 11
// speedup vs baseline: 2.0684x; 1.2251x over previous
#include <cuda_runtime.h>
#include <cuda_bf16.h>
#include <cuda_fp16.h>
#include <math.h>

#define N_NODES 100000
#define E_EDGES 1600000
#define FDIM    128
#define GGRAPHS 64
#define COUT    10
#define SCAN_B  ((N_NODES + 255) / 256)   // 391

// -------------------- scratch (static device globals) -----------------------
__device__ int   g_deg[N_NODES];
__device__ int   g_rowptr[N_NODES + 1];
__device__ int   g_cursor[N_NODES];
__device__ int   g_csr[E_EDGES];
__device__ int   g_bsum[SCAN_B];
__device__ int   g_boff[SCAN_B];
// W fp16, layout [layer][ktile 8][row 256][16 permuted]
__device__ __align__(16) __half g_wh[3 * 256 * FDIM];
// activations fp16, row-major with permuted k within each 16-group
__device__ __align__(16) __half g_h16[(size_t)N_NODES * FDIM];
__device__ __align__(16) __half g_xrh[(size_t)N_NODES * FDIM];
__device__ __align__(16) __half g_xoh[(size_t)N_NODES * FDIM];
__device__ float g_hA[(size_t)N_NODES * FDIM];   // fp32 h for pool (layer 3)
__device__ float g_pooled[GGRAPHS * FDIM];

// permuted pair base for k0 (multiple of 4): pairs at pos, pos+4
__device__ __forceinline__ int ppos(int k0) {
    int tile = k0 >> 4, kk = k0 & 15;
    return tile * 16 + 4 * ((kk & 7) >> 1) + 2 * ((kk >> 3) & 1);
}

// -------------------- CSR build ---------------------------------------------
__global__ void k_zero_deg() {
    int i = blockIdx.x * blockDim.x + threadIdx.x;
    if (i < N_NODES) g_deg[i] = 0;
}

__global__ void k_hist(const int* __restrict__ ei) {
    int e = blockIdx.x * blockDim.x + threadIdx.x;
    if (e < E_EDGES) atomicAdd(&g_deg[ei[E_EDGES + e]], 1);
}

__global__ void k_scan1() {
    __shared__ int sh[256];
    int tid = threadIdx.x;
    int i = blockIdx.x * 256 + tid;
    int v = (i < N_NODES) ? g_deg[i] : 0;
    sh[tid] = v;
    __syncthreads();
    for (int d = 128; d > 0; d >>= 1) {
        if (tid < d) sh[tid] += sh[tid + d];
        __syncthreads();
    }
    if (tid == 0) g_bsum[blockIdx.x] = sh[0];
}

__global__ void k_scan2() {
    __shared__ int s[512];
    int tid = threadIdx.x;
    int v = (tid < SCAN_B) ? g_bsum[tid] : 0;
    s[tid] = v;
    __syncthreads();
    for (int d = 1; d < 512; d <<= 1) {
        int t = (tid >= d) ? s[tid - d] : 0;
        __syncthreads();
        s[tid] += t;
        __syncthreads();
    }
    if (tid < SCAN_B) g_boff[tid] = s[tid] - v;
}

__global__ void k_scan3() {
    __shared__ int s[256];
    int tid = threadIdx.x;
    int i = blockIdx.x * 256 + tid;
    int v = (i < N_NODES) ? g_deg[i] : 0;
    s[tid] = v;
    __syncthreads();
    for (int d = 1; d < 256; d <<= 1) {
        int t = (tid >= d) ? s[tid - d] : 0;
        __syncthreads();
        s[tid] += t;
        __syncthreads();
    }
    int excl = s[tid] - v + g_boff[blockIdx.x];
    if (i < N_NODES) {
        g_rowptr[i] = excl;
        g_cursor[i] = excl;
        if (i == N_NODES - 1) g_rowptr[N_NODES] = excl + v;
    }
}

__global__ void k_fill(const int* __restrict__ ei) {
    int e = blockIdx.x * blockDim.x + threadIdx.x;
    if (e < E_EDGES) {
        int d = ei[E_EDGES + e];
        int p = atomicAdd(&g_cursor[d], 1);
        g_csr[p] = ei[e];
    }
}

// -------------------- prep: W fp16 (tile-major, permuted) -------------------
__global__ void k_conv_w(const float* __restrict__ Wr,
                         const float* __restrict__ Wo, int layer) {
    int row = blockIdx.x;           // 0..255 (0-127 Wr, 128-255 Wo)
    int k = threadIdx.x;            // 0..127
    const float* src = (row < 128) ? (Wr + (size_t)row * FDIM)
                                   : (Wo + (size_t)(row - 128) * FDIM);
    float v = src[k];
    int tile = k >> 4, kk = k & 15;
    int p = 4 * ((kk & 7) >> 1) + 2 * ((kk >> 3) & 1) + (kk & 1);
    g_wh[layer * 256 * FDIM + tile * 4096 + row * 16 + p] = __float2half(v);
}

// -------------------- prep: x -> permuted fp16 ------------------------------
__global__ void k_conv_x(const float* __restrict__ x) {
    int node = blockIdx.x * 8 + (threadIdx.x >> 5);
    if (node >= N_NODES) return;
    int lane = threadIdx.x & 31;
    float4 v = __ldg((const float4*)(x + (size_t)node * FDIM) + lane);
    int pos = ppos(lane * 4);
    __half2 a = __floats2half2_rn(v.x, v.y);
    __half2 b = __floats2half2_rn(v.z, v.w);
    *(unsigned*)(g_h16 + (size_t)node * FDIM + pos)     = *(unsigned*)&a;
    *(unsigned*)(g_h16 + (size_t)node * FDIM + pos + 4) = *(unsigned*)&b;
}

// ===================== dual fp16 GEMM =======================================
// sel=0 warps: xr = h @ Wr^T -> g_xrh.  sel=1: xo = h @ Wo^T -> g_xoh.
__device__ __forceinline__ void mma16h(float* c, const unsigned* a,
                                       unsigned b0, unsigned b1) {
    asm volatile(
        "mma.sync.aligned.m16n8k16.row.col.f32.f16.f16.f32 "
        "{%0,%1,%2,%3},{%4,%5,%6,%7},{%8,%9},{%0,%1,%2,%3};"
        : "+f"(c[0]), "+f"(c[1]), "+f"(c[2]), "+f"(c[3])
        : "r"(a[0]), "r"(a[1]), "r"(a[2]), "r"(a[3]), "r"(b0), "r"(b1));
}

__global__ __launch_bounds__(256, 2) void k_gemm_dual(int layer, int M)
{
    __shared__ __align__(16) __half sA[2][64 * 16];
    __shared__ __align__(16) __half sB[2][256 * 16];

    int tid = threadIdx.x;
    int m0 = blockIdx.x * 64;
    int warp = tid >> 5, lane = tid & 31;
    int wm = warp >> 1;          // 0..3 -> 16-row slice
    int sel = warp & 1;          // 0: Wr -> xrh, 1: Wo -> xoh
    int gq = lane >> 2, t4 = lane & 3;

    const __half* Wh = g_wh + layer * 256 * FDIM;

    // A staging: threads 0..127 copy one uint4 (8 halves) each
    int ar = tid >> 1, ac = tid & 1;          // row 0..63, chunk 0..1
    bool aok = tid < 128 && (m0 + ar) < M;
    const __half* abase = g_h16 + (size_t)(m0 + ar) * FDIM + ac * 8;
    // B staging: 512 uint4 chunks, 2 per thread
    int wr0 = tid >> 1, wc0 = (tid & 1) * 8;
    int wr1 = (tid + 256) >> 1, wc1 = ((tid + 256) & 1) * 8;

    uint4 va, wb0, wb1;
    const uint4 z4 = make_uint4(0, 0, 0, 0);
#define LOADI(i) do {                                                          \
        va  = aok ? *(const uint4*)(abase + (i) * 16) : z4;                    \
        const __half* wt = Wh + (i) * 4096;                                    \
        wb0 = *(const uint4*)(wt + wr0 * 16 + wc0);                            \
        wb1 = *(const uint4*)(wt + wr1 * 16 + wc1);                            \
    } while (0)
#define STOREI(b) do {                                                         \
        if (tid < 128) *(uint4*)(sA[b] + ar * 16 + ac * 8) = va;               \
        *(uint4*)(sB[b] + wr0 * 16 + wc0) = wb0;                               \
        *(uint4*)(sB[b] + wr1 * 16 + wc1) = wb1;                               \
    } while (0)

    float acc[16][4];
#pragma unroll
    for (int j = 0; j < 16; j++)
#pragma unroll
        for (int q = 0; q < 4; q++) acc[j][q] = 0.f;

    LOADI(0);
    STOREI(0);
    __syncthreads();

#pragma unroll
    for (int it = 0; it < 8; it++) {
        int cur = it & 1;
        if (it < 7) {
            LOADI(it + 1);
            STOREI(1 - cur);
        }
        int r1 = wm * 16 + gq;
        uint2 v1 = *(const uint2*)(sA[cur] + r1 * 16 + 4 * t4);
        uint2 v2 = *(const uint2*)(sA[cur] + (r1 + 8) * 16 + 4 * t4);
        unsigned a[4] = {v1.x, v2.x, v1.y, v2.y};
#pragma unroll
        for (int nt = 0; nt < 16; nt++) {
            int n = sel * 128 + nt * 8 + gq;
            uint2 bb = *(const uint2*)(sB[cur] + n * 16 + 4 * t4);
            mma16h(acc[nt], a, bb.x, bb.y);
        }
        __syncthreads();
    }
#undef LOADI
#undef STOREI

    __half* dst = sel ? g_xoh : g_xrh;
    int r0 = m0 + wm * 16 + gq;
#pragma unroll
    for (int nt = 0; nt < 16; nt++) {
        int cc = nt * 8 + t4 * 2;
        if (r0 < M)
            *(__half2*)(dst + (size_t)r0 * FDIM + cc) =
                __floats2half2_rn(acc[nt][0], acc[nt][1]);
        if (r0 + 8 < M)
            *(__half2*)(dst + (size_t)(r0 + 8) * FDIM + cc) =
                __floats2half2_rn(acc[nt][2], acc[nt][3]);
    }
}

// ----- fused: h_i = relu( sum_{j->i} xrh[j] + xoh[i] + bias ) ---------------
// mode 0: write permuted fp16 to g_h16 (next layer). mode 1: fp32 to outF.
__global__ void k_agg(const float* __restrict__ bias,
                      float* __restrict__ outF, int mode)
{
    int node = (blockIdx.x * blockDim.x + threadIdx.x) >> 5;
    if (node >= N_NODES) return;
    int lane = threadIdx.x & 31;
    int beg = g_rowptr[node];
    int end = g_rowptr[node + 1];
    const __half* xr = g_xrh;
    float4 a0 = make_float4(0.f, 0.f, 0.f, 0.f);
    float4 a1 = make_float4(0.f, 0.f, 0.f, 0.f);
    int e = beg;
#define GATH(acc, s) do {                                                    \
        uint2 raw = __ldg((const uint2*)(xr + (size_t)(s) * FDIM) + lane);   \
        float2 f0 = __half22float2(*(__half2*)&raw.x);                       \
        float2 f1 = __half22float2(*(__half2*)&raw.y);                       \
        acc.x += f0.x; acc.y += f0.y; acc.z += f1.x; acc.w += f1.y;          \
    } while (0)
    for (; e + 4 <= end; e += 4) {
        int s0 = g_csr[e], s1 = g_csr[e + 1], s2 = g_csr[e + 2], s3 = g_csr[e + 3];
        GATH(a0, s0); GATH(a1, s1); GATH(a0, s2); GATH(a1, s3);
    }
    for (; e < end; e++) {
        int s0 = g_csr[e];
        GATH(a0, s0);
    }
#undef GATH
    uint2 oraw = __ldg((const uint2*)(g_xoh + (size_t)node * FDIM) + lane);
    float2 o0 = __half22float2(*(__half2*)&oraw.x);
    float2 o1 = __half22float2(*(__half2*)&oraw.y);
    float4 b = __ldg((const float4*)bias + lane);
    float4 r;
    r.x = fmaxf(a0.x + a1.x + o0.x + b.x, 0.f);
    r.y = fmaxf(a0.y + a1.y + o0.y + b.y, 0.f);
    r.z = fmaxf(a0.z + a1.z + o1.x + b.z, 0.f);
    r.w = fmaxf(a0.w + a1.w + o1.y + b.w, 0.f);

    if (mode == 0) {
        int pos = ppos(lane * 4);
        __half2 p0 = __floats2half2_rn(r.x, r.y);
        __half2 p1 = __floats2half2_rn(r.z, r.w);
        *(unsigned*)(g_h16 + (size_t)node * FDIM + pos)     = *(unsigned*)&p0;
        *(unsigned*)(g_h16 + (size_t)node * FDIM + pos + 4) = *(unsigned*)&p1;
    } else {
        ((float4*)(outF + (size_t)node * FDIM))[lane] = r;
    }
}

// -------------------- mean pool (sorted batch ids, 4 row-stripes) -----------
__global__ void k_pool(const float* __restrict__ h, const int* __restrict__ batch) {
    int g = blockIdx.x;
    int t = threadIdx.x;                 // 0..511
    int col = t & 127, stripe = t >> 7;
    int lo, hi;
    {
        int key = g;
        int a = 0, b = N_NODES;
        while (a < b) { int m = (a + b) >> 1; if (batch[m] < key) a = m + 1; else b = m; }
        lo = a;
        key = g + 1; a = lo; b = N_NODES;
        while (a < b) { int m = (a + b) >> 1; if (batch[m] < key) a = m + 1; else b = m; }
        hi = a;
    }
    float s = 0.f;
    for (int n = lo + stripe; n < hi; n += 4) s += h[(size_t)n * FDIM + col];
    __shared__ float red[4][FDIM];
    red[stripe][col] = s;
    __syncthreads();
    if (stripe == 0) {
        float tot = red[0][col] + red[1][col] + red[2][col] + red[3][col];
        float c = (float)max(hi - lo, 1);
        g_pooled[g * FDIM + col] = tot / c;
    }
}

// -------------------- MLP head + log_softmax --------------------------------
__global__ void k_mlp(const float* __restrict__ Wl1, const float* __restrict__ bl1,
                      const float* __restrict__ Wl2, const float* __restrict__ bl2,
                      float* __restrict__ out)
{
    int g = blockIdx.x;
    int t = threadIdx.x;
    __shared__ float p[FDIM];
    __shared__ float h1[64];
    __shared__ float lg[COUT];
    p[t]      = g_pooled[g * FDIM + t];
    p[t + 64] = g_pooled[g * FDIM + 64 + t];
    __syncthreads();
    float s = bl1[t];
#pragma unroll 8
    for (int k = 0; k < FDIM; k++) s += p[k] * Wl1[t * FDIM + k];
    h1[t] = fmaxf(s, 0.f);
    __syncthreads();
    if (t < COUT) {
        float s2 = bl2[t];
#pragma unroll 8
        for (int k = 0; k < 64; k++) s2 += h1[k] * Wl2[t * 64 + k];
        lg[t] = s2;
    }
    __syncthreads();
    if (t == 0) {
        float mx = -INFINITY;
        for (int c = 0; c < COUT; c++) mx = fmaxf(mx, lg[c]);
        float se = 0.f;
        for (int c = 0; c < COUT; c++) se += expf(lg[c] - mx);
        float lse = logf(se) + mx;
        for (int c = 0; c < COUT; c++) out[g * COUT + c] = lg[c] - lse;
    }
}

// -------------------- launch ------------------------------------------------
extern "C" void kernel_launch(void* const* d_in, const int* in_sizes, int n_in,
                              void* d_out, int out_size)
{
    const float* x     = (const float*)d_in[0];
    const int*   ei    = (const int*)d_in[1];
    const int*   batch = (const int*)d_in[2];
    int wb = 3;
    if (n_in > 3 && in_sizes[3] <= 4) wb = 4;
    const float* W1r = (const float*)d_in[wb + 0];
    const float* b1  = (const float*)d_in[wb + 1];
    const float* W1o = (const float*)d_in[wb + 2];
    const float* W2r = (const float*)d_in[wb + 3];
    const float* b2  = (const float*)d_in[wb + 4];
    const float* W2o = (const float*)d_in[wb + 5];
    const float* W3r = (const float*)d_in[wb + 6];
    const float* b3  = (const float*)d_in[wb + 7];
    const float* W3o = (const float*)d_in[wb + 8];
    const float* Wl1 = (const float*)d_in[wb + 9];
    const float* bl1 = (const float*)d_in[wb + 10];
    const float* Wl2 = (const float*)d_in[wb + 11];
    const float* bl2 = (const float*)d_in[wb + 12];
    float* out = (float*)d_out;

    float* hA;
    cudaGetSymbolAddress((void**)&hA, g_hA);

    // prep: W fp16 + x fp16 (permuted)
    k_conv_w<<<256, 128>>>(W1r, W1o, 0);
    k_conv_w<<<256, 128>>>(W2r, W2o, 1);
    k_conv_w<<<256, 128>>>(W3r, W3o, 2);
    k_conv_x<<<(N_NODES + 7) / 8, 256>>>(x);

    // CSR build
    k_zero_deg<<<(N_NODES + 255) / 256, 256>>>();
    k_hist<<<(E_EDGES + 255) / 256, 256>>>(ei);
    k_scan1<<<SCAN_B, 256>>>();
    k_scan2<<<1, 512>>>();
    k_scan3<<<SCAN_B, 256>>>();
    k_fill<<<(E_EDGES + 255) / 256, 256>>>(ei);

    int gemmBlocks = (N_NODES + 63) / 64;
    int aggBlocks  = (N_NODES * 32 + 255) / 256;

    // layer 1
    k_gemm_dual<<<gemmBlocks, 256>>>(0, N_NODES);
    k_agg<<<aggBlocks, 256>>>(b1, nullptr, 0);
    // layer 2
    k_gemm_dual<<<gemmBlocks, 256>>>(1, N_NODES);
    k_agg<<<aggBlocks, 256>>>(b2, nullptr, 0);
    // layer 3
    k_gemm_dual<<<gemmBlocks, 256>>>(2, N_NODES);
    k_agg<<<aggBlocks, 256>>>(b3, hA, 1);

    // pool + head
    k_pool<<<GGRAPHS, 512>>>(hA, batch);
    k_mlp<<<GGRAPHS, 64>>>(Wl1, bl1, Wl2, bl2, out);
}

// round 12
// speedup vs baseline: 2.2261x; 1.0763x over previous
#include <cuda_runtime.h>
#include <cuda_bf16.h>
#include <cuda_fp16.h>
#include <math.h>

#define N_NODES 100000
#define E_EDGES 1600000
#define FDIM    128
#define GGRAPHS 64
#define COUT    10
#define SCAN_B  ((N_NODES + 255) / 256)   // 391

// -------------------- scratch (static device globals) -----------------------
__device__ int   g_deg[N_NODES];
__device__ int   g_rowptr[N_NODES + 1];
__device__ int   g_cursor[N_NODES];
__device__ int   g_csr[E_EDGES];
__device__ int   g_bsum[SCAN_B];
__device__ int   g_boff[SCAN_B];
// W fp16, layout [layer][ktile 8][row 256][16 permuted]
__device__ __align__(16) __half g_wh[3 * 256 * FDIM];
// activations fp16, row-major with permuted k within each 16-group
__device__ __align__(16) __half g_h16[(size_t)N_NODES * FDIM];
__device__ __align__(16) __half g_xrh[(size_t)N_NODES * FDIM];
__device__ __align__(16) __half g_xoh[(size_t)N_NODES * FDIM];
__device__ float g_hA[(size_t)N_NODES * FDIM];   // fp32 h for pool (layer 3)
__device__ float g_pooled[GGRAPHS * FDIM];

// permuted pair base for k0 (multiple of 4): pairs at pos, pos+4
__device__ __forceinline__ int ppos(int k0) {
    int tile = k0 >> 4, kk = k0 & 15;
    return tile * 16 + 4 * ((kk & 7) >> 1) + 2 * ((kk >> 3) & 1);
}

// -------------------- CSR build ---------------------------------------------
__global__ void k_zero_deg() {
    int i = blockIdx.x * blockDim.x + threadIdx.x;
    if (i < N_NODES) g_deg[i] = 0;
}

__global__ void k_hist(const int* __restrict__ ei) {
    int i = blockIdx.x * blockDim.x + threadIdx.x;
    if (i < E_EDGES / 4) {
        int4 d = __ldg((const int4*)(ei + E_EDGES) + i);
        atomicAdd(&g_deg[d.x], 1);
        atomicAdd(&g_deg[d.y], 1);
        atomicAdd(&g_deg[d.z], 1);
        atomicAdd(&g_deg[d.w], 1);
    }
}

__global__ void k_scan1() {
    __shared__ int sh[256];
    int tid = threadIdx.x;
    int i = blockIdx.x * 256 + tid;
    int v = (i < N_NODES) ? g_deg[i] : 0;
    sh[tid] = v;
    __syncthreads();
    for (int d = 128; d > 0; d >>= 1) {
        if (tid < d) sh[tid] += sh[tid + d];
        __syncthreads();
    }
    if (tid == 0) g_bsum[blockIdx.x] = sh[0];
}

__global__ void k_scan2() {
    __shared__ int s[512];
    int tid = threadIdx.x;
    int v = (tid < SCAN_B) ? g_bsum[tid] : 0;
    s[tid] = v;
    __syncthreads();
    for (int d = 1; d < 512; d <<= 1) {
        int t = (tid >= d) ? s[tid - d] : 0;
        __syncthreads();
        s[tid] += t;
        __syncthreads();
    }
    if (tid < SCAN_B) g_boff[tid] = s[tid] - v;
}

__global__ void k_scan3() {
    __shared__ int s[256];
    int tid = threadIdx.x;
    int i = blockIdx.x * 256 + tid;
    int v = (i < N_NODES) ? g_deg[i] : 0;
    s[tid] = v;
    __syncthreads();
    for (int d = 1; d < 256; d <<= 1) {
        int t = (tid >= d) ? s[tid - d] : 0;
        __syncthreads();
        s[tid] += t;
        __syncthreads();
    }
    int excl = s[tid] - v + g_boff[blockIdx.x];
    if (i < N_NODES) {
        g_rowptr[i] = excl;
        g_cursor[i] = excl;
        if (i == N_NODES - 1) g_rowptr[N_NODES] = excl + v;
    }
}

__global__ void k_fill(const int* __restrict__ ei) {
    int i = blockIdx.x * blockDim.x + threadIdx.x;
    if (i < E_EDGES / 4) {
        int4 s = __ldg((const int4*)ei + i);
        int4 d = __ldg((const int4*)(ei + E_EDGES) + i);
        int p;
        p = atomicAdd(&g_cursor[d.x], 1); g_csr[p] = s.x;
        p = atomicAdd(&g_cursor[d.y], 1); g_csr[p] = s.y;
        p = atomicAdd(&g_cursor[d.z], 1); g_csr[p] = s.z;
        p = atomicAdd(&g_cursor[d.w], 1); g_csr[p] = s.w;
    }
}

// -------------------- prep: W fp16 (tile-major, permuted), 3 layers ---------
__global__ void k_conv_w(const float* __restrict__ W1r, const float* __restrict__ W1o,
                         const float* __restrict__ W2r, const float* __restrict__ W2o,
                         const float* __restrict__ W3r, const float* __restrict__ W3o) {
    int layer = blockIdx.x >> 8;
    int row = blockIdx.x & 255;     // 0..255 (0-127 Wr, 128-255 Wo)
    int k = threadIdx.x;            // 0..127
    const float* Wr = (layer == 0) ? W1r : (layer == 1) ? W2r : W3r;
    const float* Wo = (layer == 0) ? W1o : (layer == 1) ? W2o : W3o;
    const float* src = (row < 128) ? (Wr + (size_t)row * FDIM)
                                   : (Wo + (size_t)(row - 128) * FDIM);
    float v = src[k];
    int tile = k >> 4, kk = k & 15;
    int p = 4 * ((kk & 7) >> 1) + 2 * ((kk >> 3) & 1) + (kk & 1);
    g_wh[layer * 256 * FDIM + tile * 4096 + row * 16 + p] = __float2half(v);
}

// -------------------- prep: x -> permuted fp16 ------------------------------
__global__ void k_conv_x(const float* __restrict__ x) {
    int node = blockIdx.x * 8 + (threadIdx.x >> 5);
    if (node >= N_NODES) return;
    int lane = threadIdx.x & 31;
    float4 v = __ldg((const float4*)(x + (size_t)node * FDIM) + lane);
    int pos = ppos(lane * 4);
    __half2 a = __floats2half2_rn(v.x, v.y);
    __half2 b = __floats2half2_rn(v.z, v.w);
    *(unsigned*)(g_h16 + (size_t)node * FDIM + pos)     = *(unsigned*)&a;
    *(unsigned*)(g_h16 + (size_t)node * FDIM + pos + 4) = *(unsigned*)&b;
}

// ===================== dual fp16 GEMM =======================================
__device__ __forceinline__ void mma16h(float* c, const unsigned* a,
                                       unsigned b0, unsigned b1) {
    asm volatile(
        "mma.sync.aligned.m16n8k16.row.col.f32.f16.f16.f32 "
        "{%0,%1,%2,%3},{%4,%5,%6,%7},{%8,%9},{%0,%1,%2,%3};"
        : "+f"(c[0]), "+f"(c[1]), "+f"(c[2]), "+f"(c[3])
        : "r"(a[0]), "r"(a[1]), "r"(a[2]), "r"(a[3]), "r"(b0), "r"(b1));
}

__global__ __launch_bounds__(256, 2) void k_gemm_dual(int layer, int M)
{
    __shared__ __align__(16) __half sA[2][64 * 16];
    __shared__ __align__(16) __half sB[2][256 * 16];

    int tid = threadIdx.x;
    int m0 = blockIdx.x * 64;
    int warp = tid >> 5, lane = tid & 31;
    int wm = warp >> 1;          // 0..3 -> 16-row slice
    int sel = warp & 1;          // 0: Wr -> xrh, 1: Wo -> xoh
    int gq = lane >> 2, t4 = lane & 3;

    const __half* Wh = g_wh + layer * 256 * FDIM;

    int ar = tid >> 1, ac = tid & 1;
    bool aok = tid < 128 && (m0 + ar) < M;
    const __half* abase = g_h16 + (size_t)(m0 + ar) * FDIM + ac * 8;
    int wr0 = tid >> 1, wc0 = (tid & 1) * 8;
    int wr1 = (tid + 256) >> 1, wc1 = ((tid + 256) & 1) * 8;

    uint4 va, wb0, wb1;
    const uint4 z4 = make_uint4(0, 0, 0, 0);
#define LOADI(i) do {                                                          \
        va  = aok ? *(const uint4*)(abase + (i) * 16) : z4;                    \
        const __half* wt = Wh + (i) * 4096;                                    \
        wb0 = *(const uint4*)(wt + wr0 * 16 + wc0);                            \
        wb1 = *(const uint4*)(wt + wr1 * 16 + wc1);                            \
    } while (0)
#define STOREI(b) do {                                                         \
        if (tid < 128) *(uint4*)(sA[b] + ar * 16 + ac * 8) = va;               \
        *(uint4*)(sB[b] + wr0 * 16 + wc0) = wb0;                               \
        *(uint4*)(sB[b] + wr1 * 16 + wc1) = wb1;                               \
    } while (0)

    float acc[16][4];
#pragma unroll
    for (int j = 0; j < 16; j++)
#pragma unroll
        for (int q = 0; q < 4; q++) acc[j][q] = 0.f;

    LOADI(0);
    STOREI(0);
    __syncthreads();

#pragma unroll
    for (int it = 0; it < 8; it++) {
        int cur = it & 1;
        if (it < 7) {
            LOADI(it + 1);
            STOREI(1 - cur);
        }
        int r1 = wm * 16 + gq;
        uint2 v1 = *(const uint2*)(sA[cur] + r1 * 16 + 4 * t4);
        uint2 v2 = *(const uint2*)(sA[cur] + (r1 + 8) * 16 + 4 * t4);
        unsigned a[4] = {v1.x, v2.x, v1.y, v2.y};
#pragma unroll
        for (int nt = 0; nt < 16; nt++) {
            int n = sel * 128 + nt * 8 + gq;
            uint2 bb = *(const uint2*)(sB[cur] + n * 16 + 4 * t4);
            mma16h(acc[nt], a, bb.x, bb.y);
        }
        __syncthreads();
    }
#undef LOADI
#undef STOREI

    __half* dst = sel ? g_xoh : g_xrh;
    int r0 = m0 + wm * 16 + gq;
#pragma unroll
    for (int nt = 0; nt < 16; nt++) {
        int cc = nt * 8 + t4 * 2;
        if (r0 < M)
            *(__half2*)(dst + (size_t)r0 * FDIM + cc) =
                __floats2half2_rn(acc[nt][0], acc[nt][1]);
        if (r0 + 8 < M)
            *(__half2*)(dst + (size_t)(r0 + 8) * FDIM + cc) =
                __floats2half2_rn(acc[nt][2], acc[nt][3]);
    }
}

// ----- fused: h_i = relu( sum_{j->i} xrh[j] + xoh[i] + bias ) ---------------
// mode 0: write permuted fp16 to g_h16 (next layer). mode 1: fp32 to outF.
__global__ void k_agg(const float* __restrict__ bias,
                      float* __restrict__ outF, int mode)
{
    int node = (blockIdx.x * blockDim.x + threadIdx.x) >> 5;
    if (node >= N_NODES) return;
    int lane = threadIdx.x & 31;
    int beg = g_rowptr[node];
    int end = g_rowptr[node + 1];
    const __half* xr = g_xrh;
    float4 a0 = make_float4(0.f, 0.f, 0.f, 0.f);
    float4 a1 = make_float4(0.f, 0.f, 0.f, 0.f);
    int e = beg;
#define ACCUM(acc, raw) do {                                                 \
        float2 f0 = __half22float2(*(__half2*)&raw.x);                       \
        float2 f1 = __half22float2(*(__half2*)&raw.y);                       \
        acc.x += f0.x; acc.y += f0.y; acc.z += f1.x; acc.w += f1.y;          \
    } while (0)
    for (; e + 8 <= end; e += 8) {
        int s0 = g_csr[e],     s1 = g_csr[e + 1], s2 = g_csr[e + 2], s3 = g_csr[e + 3];
        int s4 = g_csr[e + 4], s5 = g_csr[e + 5], s6 = g_csr[e + 6], s7 = g_csr[e + 7];
        uint2 r0 = __ldg((const uint2*)(xr + (size_t)s0 * FDIM) + lane);
        uint2 r1 = __ldg((const uint2*)(xr + (size_t)s1 * FDIM) + lane);
        uint2 r2 = __ldg((const uint2*)(xr + (size_t)s2 * FDIM) + lane);
        uint2 r3 = __ldg((const uint2*)(xr + (size_t)s3 * FDIM) + lane);
        uint2 r4 = __ldg((const uint2*)(xr + (size_t)s4 * FDIM) + lane);
        uint2 r5 = __ldg((const uint2*)(xr + (size_t)s5 * FDIM) + lane);
        uint2 r6 = __ldg((const uint2*)(xr + (size_t)s6 * FDIM) + lane);
        uint2 r7 = __ldg((const uint2*)(xr + (size_t)s7 * FDIM) + lane);
        ACCUM(a0, r0); ACCUM(a1, r1); ACCUM(a0, r2); ACCUM(a1, r3);
        ACCUM(a0, r4); ACCUM(a1, r5); ACCUM(a0, r6); ACCUM(a1, r7);
    }
    for (; e + 2 <= end; e += 2) {
        int s0 = g_csr[e], s1 = g_csr[e + 1];
        uint2 r0 = __ldg((const uint2*)(xr + (size_t)s0 * FDIM) + lane);
        uint2 r1 = __ldg((const uint2*)(xr + (size_t)s1 * FDIM) + lane);
        ACCUM(a0, r0); ACCUM(a1, r1);
    }
    if (e < end) {
        int s0 = g_csr[e];
        uint2 r0 = __ldg((const uint2*)(xr + (size_t)s0 * FDIM) + lane);
        ACCUM(a0, r0);
    }
#undef ACCUM
    uint2 oraw = __ldg((const uint2*)(g_xoh + (size_t)node * FDIM) + lane);
    float2 o0 = __half22float2(*(__half2*)&oraw.x);
    float2 o1 = __half22float2(*(__half2*)&oraw.y);
    float4 b = __ldg((const float4*)bias + lane);
    float4 r;
    r.x = fmaxf(a0.x + a1.x + o0.x + b.x, 0.f);
    r.y = fmaxf(a0.y + a1.y + o0.y + b.y, 0.f);
    r.z = fmaxf(a0.z + a1.z + o1.x + b.z, 0.f);
    r.w = fmaxf(a0.w + a1.w + o1.y + b.w, 0.f);

    if (mode == 0) {
        int pos = ppos(lane * 4);
        __half2 p0 = __floats2half2_rn(r.x, r.y);
        __half2 p1 = __floats2half2_rn(r.z, r.w);
        *(unsigned*)(g_h16 + (size_t)node * FDIM + pos)     = *(unsigned*)&p0;
        *(unsigned*)(g_h16 + (size_t)node * FDIM + pos + 4) = *(unsigned*)&p1;
    } else {
        ((float4*)(outF + (size_t)node * FDIM))[lane] = r;
    }
}

// -------------------- mean pool (sorted batch ids, 4 row-stripes) -----------
__global__ void k_pool(const float* __restrict__ h, const int* __restrict__ batch) {
    int g = blockIdx.x;
    int t = threadIdx.x;                 // 0..511
    int col = t & 127, stripe = t >> 7;
    int lo, hi;
    {
        int key = g;
        int a = 0, b = N_NODES;
        while (a < b) { int m = (a + b) >> 1; if (batch[m] < key) a = m + 1; else b = m; }
        lo = a;
        key = g + 1; a = lo; b = N_NODES;
        while (a < b) { int m = (a + b) >> 1; if (batch[m] < key) a = m + 1; else b = m; }
        hi = a;
    }
    float s = 0.f;
    for (int n = lo + stripe; n < hi; n += 4) s += h[(size_t)n * FDIM + col];
    __shared__ float red[4][FDIM];
    red[stripe][col] = s;
    __syncthreads();
    if (stripe == 0) {
        float tot = red[0][col] + red[1][col] + red[2][col] + red[3][col];
        float c = (float)max(hi - lo, 1);
        g_pooled[g * FDIM + col] = tot / c;
    }
}

// -------------------- MLP head + log_softmax --------------------------------
__global__ void k_mlp(const float* __restrict__ Wl1, const float* __restrict__ bl1,
                      const float* __restrict__ Wl2, const float* __restrict__ bl2,
                      float* __restrict__ out)
{
    int g = blockIdx.x;
    int t = threadIdx.x;
    __shared__ float p[FDIM];
    __shared__ float h1[64];
    __shared__ float lg[COUT];
    p[t]      = g_pooled[g * FDIM + t];
    p[t + 64] = g_pooled[g * FDIM + 64 + t];
    __syncthreads();
    float s = bl1[t];
#pragma unroll 8
    for (int k = 0; k < FDIM; k++) s += p[k] * Wl1[t * FDIM + k];
    h1[t] = fmaxf(s, 0.f);
    __syncthreads();
    if (t < COUT) {
        float s2 = bl2[t];
#pragma unroll 8
        for (int k = 0; k < 64; k++) s2 += h1[k] * Wl2[t * 64 + k];
        lg[t] = s2;
    }
    __syncthreads();
    if (t == 0) {
        float mx = -INFINITY;
        for (int c = 0; c < COUT; c++) mx = fmaxf(mx, lg[c]);
        float se = 0.f;
        for (int c = 0; c < COUT; c++) se += expf(lg[c] - mx);
        float lse = logf(se) + mx;
        for (int c = 0; c < COUT; c++) out[g * COUT + c] = lg[c] - lse;
    }
}

// -------------------- launch ------------------------------------------------
extern "C" void kernel_launch(void* const* d_in, const int* in_sizes, int n_in,
                              void* d_out, int out_size)
{
    const float* x     = (const float*)d_in[0];
    const int*   ei    = (const int*)d_in[1];
    const int*   batch = (const int*)d_in[2];
    int wb = 3;
    if (n_in > 3 && in_sizes[3] <= 4) wb = 4;
    const float* W1r = (const float*)d_in[wb + 0];
    const float* b1  = (const float*)d_in[wb + 1];
    const float* W1o = (const float*)d_in[wb + 2];
    const float* W2r = (const float*)d_in[wb + 3];
    const float* b2  = (const float*)d_in[wb + 4];
    const float* W2o = (const float*)d_in[wb + 5];
    const float* W3r = (const float*)d_in[wb + 6];
    const float* b3  = (const float*)d_in[wb + 7];
    const float* W3o = (const float*)d_in[wb + 8];
    const float* Wl1 = (const float*)d_in[wb + 9];
    const float* bl1 = (const float*)d_in[wb + 10];
    const float* Wl2 = (const float*)d_in[wb + 11];
    const float* bl2 = (const float*)d_in[wb + 12];
    float* out = (float*)d_out;

    float* hA;
    cudaGetSymbolAddress((void**)&hA, g_hA);

    // one-time side stream + fork/join events (host resources only)
    static cudaStream_t s2 = nullptr;
    static cudaEvent_t evFork = nullptr, evJoin = nullptr;
    if (s2 == nullptr) {
        cudaStreamCreateWithFlags(&s2, cudaStreamNonBlocking);
        cudaEventCreateWithFlags(&evFork, cudaEventDisableTiming);
        cudaEventCreateWithFlags(&evJoin, cudaEventDisableTiming);
    }

    // ---- fork: CSR build on s2, prep + layer-1 GEMM on main stream ----
    cudaEventRecord(evFork, 0);
    cudaStreamWaitEvent(s2, evFork, 0);

    k_zero_deg<<<(N_NODES + 255) / 256, 256, 0, s2>>>();
    k_hist<<<(E_EDGES / 4 + 255) / 256, 256, 0, s2>>>(ei);
    k_scan1<<<SCAN_B, 256, 0, s2>>>();
    k_scan2<<<1, 512, 0, s2>>>();
    k_scan3<<<SCAN_B, 256, 0, s2>>>();
    k_fill<<<(E_EDGES / 4 + 255) / 256, 256, 0, s2>>>(ei);
    cudaEventRecord(evJoin, s2);

    int gemmBlocks = (N_NODES + 63) / 64;
    int aggBlocks  = (N_NODES * 32 + 255) / 256;

    k_conv_w<<<768, 128>>>(W1r, W1o, W2r, W2o, W3r, W3o);
    k_conv_x<<<(N_NODES + 7) / 8, 256>>>(x);
    k_gemm_dual<<<gemmBlocks, 256>>>(0, N_NODES);

    // ---- join: agg needs CSR ----
    cudaStreamWaitEvent(0, evJoin, 0);

    // layer 1
    k_agg<<<aggBlocks, 256>>>(b1, nullptr, 0);
    // layer 2
    k_gemm_dual<<<gemmBlocks, 256>>>(1, N_NODES);
    k_agg<<<aggBlocks, 256>>>(b2, nullptr, 0);
    // layer 3
    k_gemm_dual<<<gemmBlocks, 256>>>(2, N_NODES);
    k_agg<<<aggBlocks, 256>>>(b3, hA, 1);

    // pool + head
    k_pool<<<GGRAPHS, 512>>>(hA, batch);
    k_mlp<<<GGRAPHS, 64>>>(Wl1, bl1, Wl2, bl2, out);
}

// round 15
// speedup vs baseline: 2.2581x; 1.0144x over previous
#include <cuda_runtime.h>
#include <cuda_bf16.h>
#include <cuda_fp16.h>
#include <math.h>

#define N_NODES 100000
#define E_EDGES 1600000
#define FDIM    128
#define GGRAPHS 64
#define COUT    10
#define SCAN_B  ((N_NODES + 255) / 256)   // 391

// -------------------- scratch (static device globals) -----------------------
__device__ int   g_deg[N_NODES];
__device__ int   g_rowptr[N_NODES + 1];
__device__ int   g_cursor[N_NODES];
__device__ int   g_csr[E_EDGES];
__device__ int   g_bsum[SCAN_B];
__device__ int   g_boff[SCAN_B];
// W fp16, layout [layer][ktile 8][row 256][16 permuted]
__device__ __align__(16) __half g_wh[3 * 256 * FDIM];
// activations fp16; g_h16 permuted-k between layers, linear after layer 3
__device__ __align__(16) __half g_h16[(size_t)N_NODES * FDIM];
__device__ __align__(16) __half g_xrh[(size_t)N_NODES * FDIM];
__device__ __align__(16) __half g_xoh[(size_t)N_NODES * FDIM];
__device__ float g_pooled[GGRAPHS * FDIM];

// permuted pair base for k0 (multiple of 4): pairs at pos, pos+4
__device__ __forceinline__ int ppos(int k0) {
    int tile = k0 >> 4, kk = k0 & 15;
    return tile * 16 + 4 * ((kk & 7) >> 1) + 2 * ((kk >> 3) & 1);
}

// -------------------- CSR build ---------------------------------------------
__global__ void k_zero_deg() {
    int i = blockIdx.x * blockDim.x + threadIdx.x;
    if (i < N_NODES) g_deg[i] = 0;
}

__global__ void k_hist(const int* __restrict__ ei) {
    int i = blockIdx.x * blockDim.x + threadIdx.x;
    if (i < E_EDGES / 4) {
        int4 d = __ldg((const int4*)(ei + E_EDGES) + i);
        atomicAdd(&g_deg[d.x], 1);
        atomicAdd(&g_deg[d.y], 1);
        atomicAdd(&g_deg[d.z], 1);
        atomicAdd(&g_deg[d.w], 1);
    }
}

__global__ void k_scan1() {
    __shared__ int sh[256];
    int tid = threadIdx.x;
    int i = blockIdx.x * 256 + tid;
    int v = (i < N_NODES) ? g_deg[i] : 0;
    sh[tid] = v;
    __syncthreads();
    for (int d = 128; d > 0; d >>= 1) {
        if (tid < d) sh[tid] += sh[tid + d];
        __syncthreads();
    }
    if (tid == 0) g_bsum[blockIdx.x] = sh[0];
}

__global__ void k_scan2() {
    __shared__ int s[512];
    int tid = threadIdx.x;
    int v = (tid < SCAN_B) ? g_bsum[tid] : 0;
    s[tid] = v;
    __syncthreads();
    for (int d = 1; d < 512; d <<= 1) {
        int t = (tid >= d) ? s[tid - d] : 0;
        __syncthreads();
        s[tid] += t;
        __syncthreads();
    }
    if (tid < SCAN_B) g_boff[tid] = s[tid] - v;
}

__global__ void k_scan3() {
    __shared__ int s[256];
    int tid = threadIdx.x;
    int i = blockIdx.x * 256 + tid;
    int v = (i < N_NODES) ? g_deg[i] : 0;
    s[tid] = v;
    __syncthreads();
    for (int d = 1; d < 256; d <<= 1) {
        int t = (tid >= d) ? s[tid - d] : 0;
        __syncthreads();
        s[tid] += t;
        __syncthreads();
    }
    int excl = s[tid] - v + g_boff[blockIdx.x];
    if (i < N_NODES) {
        g_rowptr[i] = excl;
        g_cursor[i] = excl;
        if (i == N_NODES - 1) g_rowptr[N_NODES] = excl + v;
    }
}

__global__ void k_fill(const int* __restrict__ ei) {
    int i = blockIdx.x * blockDim.x + threadIdx.x;
    if (i < E_EDGES / 4) {
        int4 s = __ldg((const int4*)ei + i);
        int4 d = __ldg((const int4*)(ei + E_EDGES) + i);
        int p;
        p = atomicAdd(&g_cursor[d.x], 1); g_csr[p] = s.x;
        p = atomicAdd(&g_cursor[d.y], 1); g_csr[p] = s.y;
        p = atomicAdd(&g_cursor[d.z], 1); g_csr[p] = s.z;
        p = atomicAdd(&g_cursor[d.w], 1); g_csr[p] = s.w;
    }
}

// -------------------- prep: W fp16 (tile-major, permuted), 3 layers ---------
__global__ void k_conv_w(const float* __restrict__ W1r, const float* __restrict__ W1o,
                         const float* __restrict__ W2r, const float* __restrict__ W2o,
                         const float* __restrict__ W3r, const float* __restrict__ W3o) {
    int layer = blockIdx.x >> 8;
    int row = blockIdx.x & 255;     // 0..255 (0-127 Wr, 128-255 Wo)
    int k = threadIdx.x;            // 0..127
    const float* Wr = (layer == 0) ? W1r : (layer == 1) ? W2r : W3r;
    const float* Wo = (layer == 0) ? W1o : (layer == 1) ? W2o : W3o;
    const float* src = (row < 128) ? (Wr + (size_t)row * FDIM)
                                   : (Wo + (size_t)(row - 128) * FDIM);
    float v = src[k];
    int tile = k >> 4, kk = k & 15;
    int p = 4 * ((kk & 7) >> 1) + 2 * ((kk >> 3) & 1) + (kk & 1);
    g_wh[layer * 256 * FDIM + tile * 4096 + row * 16 + p] = __float2half(v);
}

// -------------------- prep: x -> permuted fp16 ------------------------------
__global__ void k_conv_x(const float* __restrict__ x) {
    int node = blockIdx.x * 8 + (threadIdx.x >> 5);
    if (node >= N_NODES) return;
    int lane = threadIdx.x & 31;
    float4 v = __ldg((const float4*)(x + (size_t)node * FDIM) + lane);
    int pos = ppos(lane * 4);
    __half2 a = __floats2half2_rn(v.x, v.y);
    __half2 b = __floats2half2_rn(v.z, v.w);
    *(unsigned*)(g_h16 + (size_t)node * FDIM + pos)     = *(unsigned*)&a;
    *(unsigned*)(g_h16 + (size_t)node * FDIM + pos + 4) = *(unsigned*)&b;
}

// ===================== dual fp16 GEMM =======================================
__device__ __forceinline__ void mma16h(float* c, const unsigned* a,
                                       unsigned b0, unsigned b1) {
    asm volatile(
        "mma.sync.aligned.m16n8k16.row.col.f32.f16.f16.f32 "
        "{%0,%1,%2,%3},{%4,%5,%6,%7},{%8,%9},{%0,%1,%2,%3};"
        : "+f"(c[0]), "+f"(c[1]), "+f"(c[2]), "+f"(c[3])
        : "r"(a[0]), "r"(a[1]), "r"(a[2]), "r"(a[3]), "r"(b0), "r"(b1));
}

__global__ __launch_bounds__(256, 2) void k_gemm_dual(int layer, int M)
{
    __shared__ __align__(16) __half sA[2][64 * 16];
    __shared__ __align__(16) __half sB[2][256 * 16];

    int tid = threadIdx.x;
    int m0 = blockIdx.x * 64;
    int warp = tid >> 5, lane = tid & 31;
    int wm = warp >> 1;          // 0..3 -> 16-row slice
    int sel = warp & 1;          // 0: Wr -> xrh, 1: Wo -> xoh
    int gq = lane >> 2, t4 = lane & 3;

    const __half* Wh = g_wh + layer * 256 * FDIM;

    int ar = tid >> 1, ac = tid & 1;
    bool aok = tid < 128 && (m0 + ar) < M;
    const __half* abase = g_h16 + (size_t)(m0 + ar) * FDIM + ac * 8;
    int wr0 = tid >> 1, wc0 = (tid & 1) * 8;
    int wr1 = (tid + 256) >> 1, wc1 = ((tid + 256) & 1) * 8;

    uint4 va, wb0, wb1;
    const uint4 z4 = make_uint4(0, 0, 0, 0);
#define LOADI(i) do {                                                          \
        va  = aok ? *(const uint4*)(abase + (i) * 16) : z4;                    \
        const __half* wt = Wh + (i) * 4096;                                    \
        wb0 = *(const uint4*)(wt + wr0 * 16 + wc0);                            \
        wb1 = *(const uint4*)(wt + wr1 * 16 + wc1);                            \
    } while (0)
#define STOREI(b) do {                                                         \
        if (tid < 128) *(uint4*)(sA[b] + ar * 16 + ac * 8) = va;               \
        *(uint4*)(sB[b] + wr0 * 16 + wc0) = wb0;                               \
        *(uint4*)(sB[b] + wr1 * 16 + wc1) = wb1;                               \
    } while (0)

    float acc[16][4];
#pragma unroll
    for (int j = 0; j < 16; j++)
#pragma unroll
        for (int q = 0; q < 4; q++) acc[j][q] = 0.f;

    LOADI(0);
    STOREI(0);
    __syncthreads();

#pragma unroll
    for (int it = 0; it < 8; it++) {
        int cur = it & 1;
        if (it < 7) {
            LOADI(it + 1);
            STOREI(1 - cur);
        }
        int r1 = wm * 16 + gq;
        uint2 v1 = *(const uint2*)(sA[cur] + r1 * 16 + 4 * t4);
        uint2 v2 = *(const uint2*)(sA[cur] + (r1 + 8) * 16 + 4 * t4);
        unsigned a[4] = {v1.x, v2.x, v1.y, v2.y};
#pragma unroll
        for (int nt = 0; nt < 16; nt++) {
            int n = sel * 128 + nt * 8 + gq;
            uint2 bb = *(const uint2*)(sB[cur] + n * 16 + 4 * t4);
            mma16h(acc[nt], a, bb.x, bb.y);
        }
        __syncthreads();
    }
#undef LOADI
#undef STOREI

    __half* dst = sel ? g_xoh : g_xrh;
    int r0 = m0 + wm * 16 + gq;
#pragma unroll
    for (int nt = 0; nt < 16; nt++) {
        int cc = nt * 8 + t4 * 2;
        if (r0 < M)
            *(__half2*)(dst + (size_t)r0 * FDIM + cc) =
                __floats2half2_rn(acc[nt][0], acc[nt][1]);
        if (r0 + 8 < M)
            *(__half2*)(dst + (size_t)(r0 + 8) * FDIM + cc) =
                __floats2half2_rn(acc[nt][2], acc[nt][3]);
    }
}

// ----- fused: h_i = relu( sum_{j->i} xrh[j] + xoh[i] + bias ) ---------------
// Half-warp (16 lanes) per node, uint4 (8-half) loads per lane.
// mode 0: write permuted fp16 to g_h16 (next GEMM). mode 1: linear fp16 to g_h16.
__global__ void k_agg(const float* __restrict__ bias, int mode)
{
    int node = (blockIdx.x * blockDim.x + threadIdx.x) >> 4;
    if (node >= N_NODES) return;
    int lane = threadIdx.x & 15;
    int beg = g_rowptr[node];
    int end = g_rowptr[node + 1];
    const __half* xr = g_xrh;
    float acc[8];
#pragma unroll
    for (int i = 0; i < 8; i++) acc[i] = 0.f;

#define ACCUM(raw) do {                                                      \
        float2 f0 = __half22float2(*(__half2*)&raw.x);                       \
        float2 f1 = __half22float2(*(__half2*)&raw.y);                       \
        float2 f2 = __half22float2(*(__half2*)&raw.z);                       \
        float2 f3 = __half22float2(*(__half2*)&raw.w);                       \
        acc[0] += f0.x; acc[1] += f0.y; acc[2] += f1.x; acc[3] += f1.y;      \
        acc[4] += f2.x; acc[5] += f2.y; acc[6] += f3.x; acc[7] += f3.y;      \
    } while (0)

    int e = beg;
    for (; e + 4 <= end; e += 4) {
        int s0 = g_csr[e], s1 = g_csr[e + 1], s2 = g_csr[e + 2], s3 = g_csr[e + 3];
        uint4 r0 = __ldg((const uint4*)(xr + (size_t)s0 * FDIM) + lane);
        uint4 r1 = __ldg((const uint4*)(xr + (size_t)s1 * FDIM) + lane);
        uint4 r2 = __ldg((const uint4*)(xr + (size_t)s2 * FDIM) + lane);
        uint4 r3 = __ldg((const uint4*)(xr + (size_t)s3 * FDIM) + lane);
        ACCUM(r0); ACCUM(r1); ACCUM(r2); ACCUM(r3);
    }
    for (; e < end; e++) {
        int s0 = g_csr[e];
        uint4 r0 = __ldg((const uint4*)(xr + (size_t)s0 * FDIM) + lane);
        ACCUM(r0);
    }
#undef ACCUM

    uint4 oraw = __ldg((const uint4*)(g_xoh + (size_t)node * FDIM) + lane);
    float2 o0 = __half22float2(*(__half2*)&oraw.x);
    float2 o1 = __half22float2(*(__half2*)&oraw.y);
    float2 o2 = __half22float2(*(__half2*)&oraw.z);
    float2 o3 = __half22float2(*(__half2*)&oraw.w);
    float4 b0 = __ldg((const float4*)bias + lane * 2);
    float4 b1 = __ldg((const float4*)bias + lane * 2 + 1);
    float r[8];
    r[0] = fmaxf(acc[0] + o0.x + b0.x, 0.f);
    r[1] = fmaxf(acc[1] + o0.y + b0.y, 0.f);
    r[2] = fmaxf(acc[2] + o1.x + b0.z, 0.f);
    r[3] = fmaxf(acc[3] + o1.y + b0.w, 0.f);
    r[4] = fmaxf(acc[4] + o2.x + b1.x, 0.f);
    r[5] = fmaxf(acc[5] + o2.y + b1.y, 0.f);
    r[6] = fmaxf(acc[6] + o3.x + b1.z, 0.f);
    r[7] = fmaxf(acc[7] + o3.y + b1.w, 0.f);

    __half2 p0 = __floats2half2_rn(r[0], r[1]);
    __half2 p1 = __floats2half2_rn(r[2], r[3]);
    __half2 p2 = __floats2half2_rn(r[4], r[5]);
    __half2 p3 = __floats2half2_rn(r[6], r[7]);
    __half* hbase = g_h16 + (size_t)node * FDIM;
    if (mode == 0) {
        // permuted: k0 = lane*8; pairs at pos, pos+4, pos+8, pos+12
        int tile = lane >> 1;
        int pos = tile * 16 + ((lane & 1) ? 2 : 0);
        *(unsigned*)(hbase + pos)      = *(unsigned*)&p0;
        *(unsigned*)(hbase + pos + 4)  = *(unsigned*)&p1;
        *(unsigned*)(hbase + pos + 8)  = *(unsigned*)&p2;
        *(unsigned*)(hbase + pos + 12) = *(unsigned*)&p3;
    } else {
        uint4 pk;
        pk.x = *(unsigned*)&p0; pk.y = *(unsigned*)&p1;
        pk.z = *(unsigned*)&p2; pk.w = *(unsigned*)&p3;
        *(uint4*)(hbase + lane * 8) = pk;
    }
}

// -------------------- mean pool (sorted batch ids, fp16 input) --------------
__global__ void k_pool(const int* __restrict__ batch) {
    int g = blockIdx.x;
    int t = threadIdx.x;                 // 0..511
    int col = t & 127, stripe = t >> 7;
    int lo, hi;
    {
        int key = g;
        int a = 0, b = N_NODES;
        while (a < b) { int m = (a + b) >> 1; if (batch[m] < key) a = m + 1; else b = m; }
        lo = a;
        key = g + 1; a = lo; b = N_NODES;
        while (a < b) { int m = (a + b) >> 1; if (batch[m] < key) a = m + 1; else b = m; }
        hi = a;
    }
    float s = 0.f;
    for (int n = lo + stripe; n < hi; n += 4)
        s += __half2float(g_h16[(size_t)n * FDIM + col]);
    __shared__ float red[4][FDIM];
    red[stripe][col] = s;
    __syncthreads();
    if (stripe == 0) {
        float tot = red[0][col] + red[1][col] + red[2][col] + red[3][col];
        float c = (float)max(hi - lo, 1);
        g_pooled[g * FDIM + col] = tot / c;
    }
}

// -------------------- MLP head + log_softmax --------------------------------
__global__ void k_mlp(const float* __restrict__ Wl1, const float* __restrict__ bl1,
                      const float* __restrict__ Wl2, const float* __restrict__ bl2,
                      float* __restrict__ out)
{
    int g = blockIdx.x;
    int t = threadIdx.x;
    __shared__ float p[FDIM];
    __shared__ float h1[64];
    __shared__ float lg[COUT];
    p[t]      = g_pooled[g * FDIM + t];
    p[t + 64] = g_pooled[g * FDIM + 64 + t];
    __syncthreads();
    float s = bl1[t];
#pragma unroll 8
    for (int k = 0; k < FDIM; k++) s += p[k] * Wl1[t * FDIM + k];
    h1[t] = fmaxf(s, 0.f);
    __syncthreads();
    if (t < COUT) {
        float s2 = bl2[t];
#pragma unroll 8
        for (int k = 0; k < 64; k++) s2 += h1[k] * Wl2[t * 64 + k];
        lg[t] = s2;
    }
    __syncthreads();
    if (t == 0) {
        float mx = -INFINITY;
        for (int c = 0; c < COUT; c++) mx = fmaxf(mx, lg[c]);
        float se = 0.f;
        for (int c = 0; c < COUT; c++) se += expf(lg[c] - mx);
        float lse = logf(se) + mx;
        for (int c = 0; c < COUT; c++) out[g * COUT + c] = lg[c] - lse;
    }
}

// -------------------- launch ------------------------------------------------
extern "C" void kernel_launch(void* const* d_in, const int* in_sizes, int n_in,
                              void* d_out, int out_size)
{
    const float* x     = (const float*)d_in[0];
    const int*   ei    = (const int*)d_in[1];
    const int*   batch = (const int*)d_in[2];
    int wb = 3;
    if (n_in > 3 && in_sizes[3] <= 4) wb = 4;
    const float* W1r = (const float*)d_in[wb + 0];
    const float* b1  = (const float*)d_in[wb + 1];
    const float* W1o = (const float*)d_in[wb + 2];
    const float* W2r = (const float*)d_in[wb + 3];
    const float* b2  = (const float*)d_in[wb + 4];
    const float* W2o = (const float*)d_in[wb + 5];
    const float* W3r = (const float*)d_in[wb + 6];
    const float* b3  = (const float*)d_in[wb + 7];
    const float* W3o = (const float*)d_in[wb + 8];
    const float* Wl1 = (const float*)d_in[wb + 9];
    const float* bl1 = (const float*)d_in[wb + 10];
    const float* Wl2 = (const float*)d_in[wb + 11];
    const float* bl2 = (const float*)d_in[wb + 12];
    float* out = (float*)d_out;

    // one-time side stream + fork/join events (host resources only)
    static cudaStream_t s2 = nullptr;
    static cudaEvent_t evFork = nullptr, evJoin = nullptr;
    if (s2 == nullptr) {
        cudaStreamCreateWithFlags(&s2, cudaStreamNonBlocking);
        cudaEventCreateWithFlags(&evFork, cudaEventDisableTiming);
        cudaEventCreateWithFlags(&evJoin, cudaEventDisableTiming);
    }

    // ---- fork: CSR build on s2, prep + layer-1 GEMM on main stream ----
    cudaEventRecord(evFork, 0);
    cudaStreamWaitEvent(s2, evFork, 0);

    k_zero_deg<<<(N_NODES + 255) / 256, 256, 0, s2>>>();
    k_hist<<<(E_EDGES / 4 + 255) / 256, 256, 0, s2>>>(ei);
    k_scan1<<<SCAN_B, 256, 0, s2>>>();
    k_scan2<<<1, 512, 0, s2>>>();
    k_scan3<<<SCAN_B, 256, 0, s2>>>();
    k_fill<<<(E_EDGES / 4 + 255) / 256, 256, 0, s2>>>(ei);
    cudaEventRecord(evJoin, s2);

    int gemmBlocks = (N_NODES + 63) / 64;
    int aggBlocks  = (N_NODES * 16 + 255) / 256;

    k_conv_w<<<768, 128>>>(W1r, W1o, W2r, W2o, W3r, W3o);
    k_conv_x<<<(N_NODES + 7) / 8, 256>>>(x);
    k_gemm_dual<<<gemmBlocks, 256>>>(0, N_NODES);

    // ---- join: agg needs CSR ----
    cudaStreamWaitEvent(0, evJoin, 0);

    // layer 1
    k_agg<<<aggBlocks, 256>>>(b1, 0);
    // layer 2
    k_gemm_dual<<<gemmBlocks, 256>>>(1, N_NODES);
    k_agg<<<aggBlocks, 256>>>(b2, 0);
    // layer 3
    k_gemm_dual<<<gemmBlocks, 256>>>(2, N_NODES);
    k_agg<<<aggBlocks, 256>>>(b3, 1);

    // pool + head
    k_pool<<<GGRAPHS, 512>>>(batch);
    k_mlp<<<GGRAPHS, 64>>>(Wl1, bl1, Wl2, bl2, out);
}